// round 3
// baseline (speedup 1.0000x reference)
#include <cuda_runtime.h>
#include <math.h>

#define HW_ 16384

// ---------------- scratch (static device globals; no allocation) ----------------
__device__ float g_actv[4*128*HW_];
__device__ float g_spg[4*64*HW_];
__device__ float g_spb[4*64*HW_];
__device__ float g_noiseT[4*HW_];
__device__ float g_mean[256];
__device__ float g_rstd[256];
__device__ float g_mmu[4*6*512];
__device__ float g_Gg[4*6*576];
__device__ float g_Gb[4*6*576];
__device__ unsigned char g_region[4*HW_];
__device__ float g_wT[9*128*128];     // spade weights [tap][ic][ocv]
__device__ float g_cwT[2*9*64*512];   // conv_{gamma,beta}_w as [table][tap][oc][d]

// ---------------- f32x2 helpers ----------------
__device__ __forceinline__ unsigned long long pk2(float a, float b){
    unsigned long long r; asm("mov.b64 %0, {%1,%2};" : "=l"(r) : "f"(a), "f"(b)); return r;
}
__device__ __forceinline__ void upk2(unsigned long long v, float& a, float& b){
    asm("mov.b64 {%0,%1}, %2;" : "=f"(a), "=f"(b) : "l"(v));
}
__device__ __forceinline__ void fma2(unsigned long long& d, unsigned long long a, unsigned long long b){
    asm("fma.rn.f32x2 %0, %1, %2, %3;" : "=l"(d) : "l"(a), "l"(b), "l"(d));
}
__device__ __forceinline__ void add2(unsigned long long& d, unsigned long long a){
    asm("add.rn.f32x2 %0, %1, %2;" : "=l"(d) : "l"(a), "l"(d));
}

// ---------------- K0: noise (B,W,H,1) -> [b][h][w] ----------------
__global__ void noiseT_kernel(const float* __restrict__ noise){
    int i = blockIdx.x*256 + threadIdx.x;            // 65536
    int b = i >> 14, p = i & 16383;
    int h = p >> 7, w = p & 127;
    g_noiseT[i] = noise[(b<<14) + (w<<7) + h];
}

// ---------------- K1: instance-norm stats of xn = x + nv*noiseT ----------------
__global__ void stats_kernel(const float* __restrict__ x, const float* __restrict__ nvar){
    int bc = blockIdx.x; int b = bc >> 6, c = bc & 63;
    float nv = nvar[c];
    const float4* xp = reinterpret_cast<const float4*>(x + (size_t)bc*HW_);
    const float4* np = reinterpret_cast<const float4*>(g_noiseT + (size_t)b*HW_);
    float s = 0.f, ss = 0.f;
    for(int i = threadIdx.x; i < HW_/4; i += 256){
        float4 xv = xp[i]; float4 nn = np[i];
        float v;
        v = xv.x + nv*nn.x; s += v; ss += v*v;
        v = xv.y + nv*nn.y; s += v; ss += v*v;
        v = xv.z + nv*nn.z; s += v; ss += v*v;
        v = xv.w + nv*nn.w; s += v; ss += v*v;
    }
    __shared__ float rs[256], rq[256];
    rs[threadIdx.x] = s; rq[threadIdx.x] = ss;
    __syncthreads();
    for(int st = 128; st > 0; st >>= 1){
        if(threadIdx.x < st){ rs[threadIdx.x] += rs[threadIdx.x+st]; rq[threadIdx.x] += rq[threadIdx.x+st]; }
        __syncthreads();
    }
    if(threadIdx.x == 0){
        float m = rs[0]*(1.f/HW_);
        float var = rq[0]*(1.f/HW_) - m*m;
        g_mean[bc] = m;
        g_rstd[bc] = rsqrtf(var + 1e-5f);
    }
}

// ---------------- K2: middle_mu[b,f,o] = relu(codes . fc_w[f,o,:] + fc_b) ----------------
__global__ void __launch_bounds__(256) mmu_kernel(const float* __restrict__ codes,
                                                  const float* __restrict__ fcw,
                                                  const float* __restrict__ fcb){
    int bf = blockIdx.x; int f = bf % 6;
    int lane = threadIdx.x & 31, warp = threadIdx.x >> 5;
    float c[16];
    const float4* cp = reinterpret_cast<const float4*>(codes + (size_t)bf*512);
    #pragma unroll
    for(int it=0; it<4; it++){
        float4 v = cp[it*32 + lane];
        c[it*4+0]=v.x; c[it*4+1]=v.y; c[it*4+2]=v.z; c[it*4+3]=v.w;
    }
    for(int o = warp; o < 512; o += 8){
        const float4* wp = reinterpret_cast<const float4*>(fcw + ((size_t)f*512 + o)*512);
        float s = 0.f;
        #pragma unroll
        for(int it=0; it<4; it++){
            float4 w = wp[it*32 + lane];
            s += w.x*c[it*4] + w.y*c[it*4+1] + w.z*c[it*4+2] + w.w*c[it*4+3];
        }
        #pragma unroll
        for(int st=16; st>0; st>>=1) s += __shfl_xor_sync(0xffffffffu, s, st);
        if(lane==0) g_mmu[bf*512+o] = fmaxf(s + fcb[f*512+o], 0.f);
    }
}

// ---------------- K3a: transpose conv weights to [table][tap][oc][d] ----------------
__global__ void cwt_kernel(const float* __restrict__ wg, const float* __restrict__ wb){
    int i = blockIdx.x*256 + threadIdx.x;            // 589824 total
    int table = i / 294912; int r = i % 294912;
    int tap = r / 32768; int rem = r % 32768;
    int oc = rem >> 9; int d = rem & 511;
    const float* w = table ? wb : wg;
    g_cwT[i] = w[(size_t)oc*4608 + d*9 + tap];
}

// ---------------- K3b: G[b,f,tap*64+oc] = sum_d cwT[.,tap,oc,d]*mmu[b,f,d] ----------------
__global__ void __launch_bounds__(256) gtab_kernel(){
    int bf = blockIdx.x;     // 0..23
    int rg = blockIdx.y;     // 0..15
    int lane = threadIdx.x & 31, warp = threadIdx.x >> 5;
    float m[16];
    const float4* mp = reinterpret_cast<const float4*>(g_mmu + (size_t)bf*512);
    #pragma unroll
    for(int it=0; it<4; it++){
        float4 v = mp[it*32 + lane];
        m[it*4]=v.x; m[it*4+1]=v.y; m[it*4+2]=v.z; m[it*4+3]=v.w;
    }
    int row0 = rg*72 + warp*9;
    for(int rr=0; rr<9; rr++){
        int rid = row0 + rr;
        int table = rid / 576; int k = rid % 576;
        const float4* wp = reinterpret_cast<const float4*>(g_cwT + (size_t)table*294912 + (size_t)k*512);
        float s = 0.f;
        #pragma unroll
        for(int it=0; it<4; it++){
            float4 w = wp[it*32+lane];
            s += w.x*m[it*4] + w.y*m[it*4+1] + w.z*m[it*4+2] + w.w*m[it*4+3];
        }
        #pragma unroll
        for(int st=16; st>0; st>>=1) s += __shfl_xor_sync(0xffffffffu, s, st);
        if(lane==0){ if(table) g_Gb[bf*576+k] = s; else g_Gg[bf*576+k] = s; }
    }
}

// ---------------- K4: region id map (last nonzero feature; 6 = none) ----------------
__global__ void region_kernel(const float* __restrict__ segmap){
    int i = blockIdx.x*256 + threadIdx.x;            // 65536
    int b = i >> 14, p = i & 16383;
    unsigned char r = 6;
    #pragma unroll
    for(int j = 0; j < 6; j++)
        if(segmap[((size_t)(b*6+j)<<14) + p] != 0.f) r = (unsigned char)j;
    g_region[i] = r;
}

// ---------------- K5: spade weights -> [tap][ic][ocv] ----------------
__global__ void wtrans_kernel(const float* __restrict__ wg, const float* __restrict__ wb){
    int i = blockIdx.x*256 + threadIdx.x;            // 147456
    int tap = i / 16384; int rem = i % 16384;
    int ic = rem >> 7; int ocv = rem & 127;
    float v = (ocv < 64) ? wg[(size_t)ocv*1152 + ic*9 + tap]
                         : wb[(size_t)(ocv-64)*1152 + ic*9 + tap];
    g_wT[i] = v;
}

// ---------------- K6: actv = relu(conv3x3(mask 3->128)) ----------------
__global__ void __launch_bounds__(128) actv_kernel(const float* __restrict__ mask,
                                                   const float* __restrict__ sw,
                                                   const float* __restrict__ sb){
    __shared__ float swt[3456];
    __shared__ float sbias[128];
    int y = blockIdx.x, b = blockIdx.y, x = threadIdx.x;
    for(int i = threadIdx.x; i < 3456; i += 128) swt[i] = sw[i];
    sbias[threadIdx.x] = sb[threadIdx.x];
    float mv[27];
    #pragma unroll
    for(int m = 0; m < 3; m++)
        #pragma unroll
        for(int ky = 0; ky < 3; ky++)
            #pragma unroll
            for(int kx = 0; kx < 3; kx++){
                int gy = y + ky - 1, gx = x + kx - 1;
                mv[m*9 + ky*3 + kx] = (gy >= 0 && gy < 128 && gx >= 0 && gx < 128)
                    ? mask[((size_t)(b*3+m)<<14) + (gy<<7) + gx] : 0.f;
            }
    __syncthreads();
    for(int ic = 0; ic < 128; ic++){
        float acc = sbias[ic];
        const float* wr = &swt[ic*27];
        #pragma unroll
        for(int k = 0; k < 27; k++) acc += mv[k]*wr[k];
        g_actv[((size_t)(b*128+ic)<<14) + (y<<7) + x] = fmaxf(acc, 0.f);
    }
}

// ---------------- K7: SPADE conv 128->128 (64 gamma | 64 beta), f32x2 FMA ----------------
__global__ void __launch_bounds__(256) spade_kernel(const float* __restrict__ gbias,
                                                    const float* __restrict__ bbias){
    __shared__ __align__(16) float s_w[9216];        // [tap][icl][ocv]
    __shared__ float s_actv[8][10][18];
    int b = blockIdx.z;
    int x0 = blockIdx.x*16, y0 = blockIdx.y*8;
    int tid = threadIdx.x;
    int ocg = tid >> 4, pg = tid & 15;
    int o0 = ocg*8;
    unsigned long long acc[8][4];
    #pragma unroll
    for(int pp=0; pp<8; pp++){ acc[pp][0]=0ull; acc[pp][1]=0ull; acc[pp][2]=0ull; acc[pp][3]=0ull; }

    for(int icc = 0; icc < 16; icc++){
        int ic0 = icc*8;
        __syncthreads();
        for(int i = tid; i < 1440; i += 256){
            int icl = i/180, rem = i%180, ry = rem/18, cx = rem%18;
            int gy = y0 - 1 + ry, gx = x0 - 1 + cx;
            float v = 0.f;
            if(gy >= 0 && gy < 128 && gx >= 0 && gx < 128)
                v = g_actv[((size_t)(b*128 + ic0 + icl)<<14) + (gy<<7) + gx];
            s_actv[icl][ry][cx] = v;
        }
        #pragma unroll
        for(int it = 0; it < 36; it++){
            int i = tid + it*256;
            int tap = i >> 10, rem = i & 1023;
            s_w[i] = g_wT[tap*16384 + ic0*128 + rem];
        }
        __syncthreads();

        for(int icl = 0; icl < 8; icl++){
            #pragma unroll
            for(int dx = 0; dx < 3; dx++){
                unsigned long long a2[10];
                #pragma unroll
                for(int r = 0; r < 10; r++){
                    float v = s_actv[icl][r][pg+dx];
                    a2[r] = pk2(v, v);
                }
                #pragma unroll
                for(int dy = 0; dy < 3; dy++){
                    int tap = dy*3+dx;
                    const ulonglong2* wp = reinterpret_cast<const ulonglong2*>(&s_w[tap*1024 + icl*128 + o0]);
                    ulonglong2 wA = wp[0], wB = wp[1];
                    #pragma unroll
                    for(int pp = 0; pp < 8; pp++){
                        unsigned long long av = a2[pp+dy];
                        fma2(acc[pp][0], av, wA.x);
                        fma2(acc[pp][1], av, wA.y);
                        fma2(acc[pp][2], av, wB.x);
                        fma2(acc[pp][3], av, wB.y);
                    }
                }
            }
        }
    }

    int xg = x0 + pg;
    #pragma unroll
    for(int pp = 0; pp < 8; pp++){
        int yg = y0 + pp;
        #pragma unroll
        for(int j = 0; j < 4; j++){
            float lo, hi; upk2(acc[pp][j], lo, hi);
            int v0 = o0 + 2*j, v1 = v0 + 1;
            if(v0 < 64){
                g_spg[((size_t)(b*64 + v0)<<14) + (yg<<7) + xg] = lo + gbias[v0];
                g_spg[((size_t)(b*64 + v1)<<14) + (yg<<7) + xg] = hi + gbias[v1];
            }else{
                g_spb[((size_t)(b*64 + v0 - 64)<<14) + (yg<<7) + xg] = lo + bbias[v0-64];
                g_spb[((size_t)(b*64 + v1 - 64)<<14) + (yg<<7) + xg] = hi + bbias[v1-64];
            }
        }
    }
}

// ---------------- K8: fused region-gather + instance-norm + blend ----------------
__global__ void __launch_bounds__(128) final_kernel(const float* __restrict__ x,
        const float* __restrict__ nvar, const float* __restrict__ cgb,
        const float* __restrict__ cbb, const float* __restrict__ bg,
        const float* __restrict__ bb2, float* __restrict__ out){
    __shared__ __align__(16) float sGg[7*584];
    __shared__ __align__(16) float sGb[7*584];
    __shared__ float s_mean[64], s_rstd[64], s_nv[64], s_gb[64], s_bb[64];
    int b = blockIdx.y, y = blockIdx.x, tidx = threadIdx.x;
    for(int i = tidx; i < 7*584; i += 128){
        int r = i/584, k = i%584;
        float vg = 0.f, vb = 0.f;
        if(r < 6 && k < 576){ vg = g_Gg[(b*6+r)*576 + k]; vb = g_Gb[(b*6+r)*576 + k]; }
        sGg[i] = vg; sGb[i] = vb;
    }
    if(tidx < 64){
        s_mean[tidx] = g_mean[b*64+tidx]; s_rstd[tidx] = g_rstd[b*64+tidx];
        s_nv[tidx] = nvar[tidx]; s_gb[tidx] = cgb[tidx]; s_bb[tidx] = cbb[tidx];
    }
    __syncthreads();
    float ga = 1.f/(1.f + expf(-bg[0]));
    float ba = 1.f/(1.f + expf(-bb2[0]));
    int xcol = tidx;
    int base[9];
    #pragma unroll
    for(int tap = 0; tap < 9; tap++){
        int dy = tap/3 - 1, dx = tap%3 - 1;
        int yy = y + dy, xx = xcol + dx;
        int r = 6;
        if(yy >= 0 && yy < 128 && xx >= 0 && xx < 128) r = g_region[(b<<14) + (yy<<7) + xx];
        base[tap] = r*584 + tap*64;
    }
    float nz = g_noiseT[(b<<14) + (y<<7) + xcol];
    size_t pix = (size_t)(y<<7) + xcol;
    for(int j = 0; j < 16; j++){
        unsigned long long ag0=0ull, ag1=0ull, ab0=0ull, ab1=0ull;
        #pragma unroll
        for(int tap = 0; tap < 9; tap++){
            const ulonglong2* pgp = reinterpret_cast<const ulonglong2*>(&sGg[base[tap] + j*4]);
            const ulonglong2* pbp = reinterpret_cast<const ulonglong2*>(&sGb[base[tap] + j*4]);
            ulonglong2 vg = *pgp, vb = *pbp;
            add2(ag0, vg.x); add2(ag1, vg.y);
            add2(ab0, vb.x); add2(ab1, vb.y);
        }
        float g4[4], b4[4];
        upk2(ag0, g4[0], g4[1]); upk2(ag1, g4[2], g4[3]);
        upk2(ab0, b4[0], b4[1]); upk2(ab1, b4[2], b4[3]);
        #pragma unroll
        for(int k = 0; k < 4; k++){
            int c = j*4 + k;
            size_t idx = (((size_t)(b*64 + c))<<14) + pix;
            float xv = x[idx] + s_nv[c]*nz;
            float xn = (xv - s_mean[c])*s_rstd[c];
            float gf = ga*(g4[k] + s_gb[c]) + (1.f - ga)*g_spg[idx];
            float bf = ba*(b4[k] + s_bb[c]) + (1.f - ba)*g_spb[idx];
            out[idx] = xn*(1.f + gf) + bf;
        }
    }
}

extern "C" void kernel_launch(void* const* d_in, const int* in_sizes, int n_in,
                              void* d_out, int out_size) {
    const float* x      = (const float*)d_in[0];
    const float* segmap = (const float*)d_in[1];
    const float* mask   = (const float*)d_in[2];
    const float* codes  = (const float*)d_in[3];
    const float* noise  = (const float*)d_in[4];
    const float* nvar   = (const float*)d_in[5];
    const float* fc_w   = (const float*)d_in[6];
    const float* fc_b   = (const float*)d_in[7];
    const float* cg_w   = (const float*)d_in[8];
    const float* cg_b   = (const float*)d_in[9];
    const float* cb_w   = (const float*)d_in[10];
    const float* cb_b   = (const float*)d_in[11];
    const float* ss_w   = (const float*)d_in[12];
    const float* ss_b   = (const float*)d_in[13];
    const float* sg_w   = (const float*)d_in[14];
    const float* sg_b   = (const float*)d_in[15];
    const float* sb_w   = (const float*)d_in[16];
    const float* sb_b   = (const float*)d_in[17];
    const float* bgam   = (const float*)d_in[18];
    const float* bbet   = (const float*)d_in[19];
    float* out = (float*)d_out;

    noiseT_kernel<<<256, 256>>>(noise);
    stats_kernel<<<256, 256>>>(x, nvar);
    mmu_kernel<<<24, 256>>>(codes, fc_w, fc_b);
    cwt_kernel<<<2304, 256>>>(cg_w, cb_w);
    gtab_kernel<<<dim3(24,16), 256>>>();
    region_kernel<<<256, 256>>>(segmap);
    wtrans_kernel<<<576, 256>>>(sg_w, sb_w);
    actv_kernel<<<dim3(128,4), 128>>>(mask, ss_w, ss_b);
    spade_kernel<<<dim3(8,16,4), 256>>>(sg_b, sb_b);
    final_kernel<<<dim3(128,4), 128>>>(x, nvar, cg_b, cb_b, bgam, bbet, out);
}

// round 6
// speedup vs baseline: 2.6475x; 2.6475x over previous
#include <cuda_runtime.h>
#include <cuda_bf16.h>
#include <math.h>

#define HW_ 16384

// ---------------- scratch (static device globals; no allocation) ----------------
__device__ __nv_bfloat16 g_actvB[4*HW_*128];   // NHWC bf16: [b][y][x][ic]
__device__ __nv_bfloat16 g_wBp[9*128*128];     // [tap][oc][ic] bf16
__device__ float g_spg[4*64*HW_];
__device__ float g_spb[4*64*HW_];
__device__ float g_noiseT[4*HW_];
__device__ float g_mean[256];
__device__ float g_rstd[256];
__device__ float g_mmu[4*6*512];
__device__ float g_Gg[4*6*576];
__device__ float g_Gb[4*6*576];
__device__ unsigned char g_region[4*HW_];
__device__ float g_cwT[2*9*64*512];            // conv_{gamma,beta}_w as [table][tap][oc][d]

// ---------------- f32x2 helpers (final_kernel) ----------------
__device__ __forceinline__ void upk2(unsigned long long v, float& a, float& b){
    asm("mov.b64 {%0,%1}, %2;" : "=f"(a), "=f"(b) : "l"(v));
}
__device__ __forceinline__ void add2(unsigned long long& d, unsigned long long a){
    asm("add.rn.f32x2 %0, %1, %2;" : "=l"(d) : "l"(a), "l"(d));
}

// ---------------- mma / ldmatrix / cp.async helpers (sm_80+ portable) ----------------
__device__ __forceinline__ unsigned smem_u32(const void* p){
    unsigned r; asm("{ .reg .u64 t; cvta.to.shared.u64 t, %1; cvt.u32.u64 %0, t; }" : "=r"(r) : "l"(p));
    return r;
}
__device__ __forceinline__ void ldmx4(unsigned* r, unsigned addr){
    asm volatile("ldmatrix.sync.aligned.m8n8.x4.shared.b16 {%0,%1,%2,%3}, [%4];"
        : "=r"(r[0]),"=r"(r[1]),"=r"(r[2]),"=r"(r[3]) : "r"(addr));
}
__device__ __forceinline__ void ldmx2(unsigned* r, unsigned addr){
    asm volatile("ldmatrix.sync.aligned.m8n8.x2.shared.b16 {%0,%1}, [%2];"
        : "=r"(r[0]),"=r"(r[1]) : "r"(addr));
}
__device__ __forceinline__ void mma16816(float* d, const unsigned* a, const unsigned* bq){
    asm volatile("mma.sync.aligned.m16n8k16.row.col.f32.bf16.bf16.f32 "
        "{%0,%1,%2,%3}, {%4,%5,%6,%7}, {%8,%9}, {%0,%1,%2,%3};"
        : "+f"(d[0]),"+f"(d[1]),"+f"(d[2]),"+f"(d[3])
        : "r"(a[0]),"r"(a[1]),"r"(a[2]),"r"(a[3]), "r"(bq[0]),"r"(bq[1]));
}
__device__ __forceinline__ void cpa16(unsigned dst, const void* src){
    asm volatile("cp.async.cg.shared.global [%0], [%1], 16;" :: "r"(dst), "l"(src) : "memory");
}
#define CPA_COMMIT() asm volatile("cp.async.commit_group;" ::: "memory")
#define CPA_WAIT0()  asm volatile("cp.async.wait_group 0;" ::: "memory")

// ---------------- K0: noise (B,W,H,1) -> [b][h][w] ----------------
__global__ void noiseT_kernel(const float* __restrict__ noise){
    int i = blockIdx.x*256 + threadIdx.x;
    int b = i >> 14, p = i & 16383;
    int h = p >> 7, w = p & 127;
    g_noiseT[i] = noise[(b<<14) + (w<<7) + h];
}

// ---------------- K1: instance-norm stats ----------------
__global__ void stats_kernel(const float* __restrict__ x, const float* __restrict__ nvar){
    int bc = blockIdx.x; int b = bc >> 6, c = bc & 63;
    float nv = nvar[c];
    const float4* xp = reinterpret_cast<const float4*>(x + (size_t)bc*HW_);
    const float4* np = reinterpret_cast<const float4*>(g_noiseT + (size_t)b*HW_);
    float s = 0.f, ss = 0.f;
    for(int i = threadIdx.x; i < HW_/4; i += 256){
        float4 xv = xp[i]; float4 nn = np[i];
        float v;
        v = xv.x + nv*nn.x; s += v; ss += v*v;
        v = xv.y + nv*nn.y; s += v; ss += v*v;
        v = xv.z + nv*nn.z; s += v; ss += v*v;
        v = xv.w + nv*nn.w; s += v; ss += v*v;
    }
    __shared__ float rs[256], rq[256];
    rs[threadIdx.x] = s; rq[threadIdx.x] = ss;
    __syncthreads();
    for(int st = 128; st > 0; st >>= 1){
        if(threadIdx.x < st){ rs[threadIdx.x] += rs[threadIdx.x+st]; rq[threadIdx.x] += rq[threadIdx.x+st]; }
        __syncthreads();
    }
    if(threadIdx.x == 0){
        float m = rs[0]*(1.f/HW_);
        float var = rq[0]*(1.f/HW_) - m*m;
        g_mean[bc] = m;
        g_rstd[bc] = rsqrtf(var + 1e-5f);
    }
}

// ---------------- K2: middle_mu ----------------
__global__ void __launch_bounds__(256) mmu_kernel(const float* __restrict__ codes,
                                                  const float* __restrict__ fcw,
                                                  const float* __restrict__ fcb){
    int bf = blockIdx.x; int f = bf % 6;
    int lane = threadIdx.x & 31, warp = threadIdx.x >> 5;
    float c[16];
    const float4* cp = reinterpret_cast<const float4*>(codes + (size_t)bf*512);
    #pragma unroll
    for(int it=0; it<4; it++){
        float4 v = cp[it*32 + lane];
        c[it*4+0]=v.x; c[it*4+1]=v.y; c[it*4+2]=v.z; c[it*4+3]=v.w;
    }
    for(int o = warp; o < 512; o += 8){
        const float4* wp = reinterpret_cast<const float4*>(fcw + ((size_t)f*512 + o)*512);
        float s = 0.f;
        #pragma unroll
        for(int it=0; it<4; it++){
            float4 w = wp[it*32 + lane];
            s += w.x*c[it*4] + w.y*c[it*4+1] + w.z*c[it*4+2] + w.w*c[it*4+3];
        }
        #pragma unroll
        for(int st=16; st>0; st>>=1) s += __shfl_xor_sync(0xffffffffu, s, st);
        if(lane==0) g_mmu[bf*512+o] = fmaxf(s + fcb[f*512+o], 0.f);
    }
}

// ---------------- K3a: conv weights -> [table][tap][oc][d] ----------------
__global__ void cwt_kernel(const float* __restrict__ wg, const float* __restrict__ wb){
    int i = blockIdx.x*256 + threadIdx.x;            // 589824
    int table = i / 294912; int r = i % 294912;
    int tap = r / 32768; int rem = r % 32768;
    int oc = rem >> 9; int d = rem & 511;
    const float* w = table ? wb : wg;
    g_cwT[i] = w[(size_t)oc*4608 + d*9 + tap];
}

// ---------------- K3b: G tables ----------------
__global__ void __launch_bounds__(256) gtab_kernel(){
    int bf = blockIdx.x;
    int rg = blockIdx.y;
    int lane = threadIdx.x & 31, warp = threadIdx.x >> 5;
    float m[16];
    const float4* mp = reinterpret_cast<const float4*>(g_mmu + (size_t)bf*512);
    #pragma unroll
    for(int it=0; it<4; it++){
        float4 v = mp[it*32 + lane];
        m[it*4]=v.x; m[it*4+1]=v.y; m[it*4+2]=v.z; m[it*4+3]=v.w;
    }
    int row0 = rg*72 + warp*9;
    for(int rr=0; rr<9; rr++){
        int rid = row0 + rr;
        int table = rid / 576; int k = rid % 576;
        const float4* wp = reinterpret_cast<const float4*>(g_cwT + (size_t)table*294912 + (size_t)k*512);
        float s = 0.f;
        #pragma unroll
        for(int it=0; it<4; it++){
            float4 w = wp[it*32+lane];
            s += w.x*m[it*4] + w.y*m[it*4+1] + w.z*m[it*4+2] + w.w*m[it*4+3];
        }
        #pragma unroll
        for(int st=16; st>0; st>>=1) s += __shfl_xor_sync(0xffffffffu, s, st);
        if(lane==0){ if(table) g_Gb[bf*576+k] = s; else g_Gg[bf*576+k] = s; }
    }
}

// ---------------- K4: region map ----------------
__global__ void region_kernel(const float* __restrict__ segmap){
    int i = blockIdx.x*256 + threadIdx.x;
    int b = i >> 14, p = i & 16383;
    unsigned char r = 6;
    #pragma unroll
    for(int j = 0; j < 6; j++)
        if(segmap[((size_t)(b*6+j)<<14) + p] != 0.f) r = (unsigned char)j;
    g_region[i] = r;
}

// ---------------- K5: spade weights -> [tap][oc][ic] bf16 ----------------
__global__ void wtrans_kernel(const float* __restrict__ wg, const float* __restrict__ wb){
    int i = blockIdx.x*256 + threadIdx.x;            // 147456
    int tap = i >> 14; int oc = (i >> 7) & 127; int ic = i & 127;
    float v = (oc < 64) ? wg[(size_t)oc*1152 + ic*9 + tap]
                        : wb[(size_t)(oc-64)*1152 + ic*9 + tap];
    g_wBp[i] = __float2bfloat16(v);
}

// ---------------- K6: actv = relu(conv3x3(mask 3->128)) -> NHWC bf16 ----------------
__global__ void __launch_bounds__(128) actv_kernel(const float* __restrict__ mask,
                                                   const float* __restrict__ sw,
                                                   const float* __restrict__ sb){
    __shared__ float swt[3456];
    __shared__ float sbias[128];
    int y = blockIdx.x, b = blockIdx.y, x = threadIdx.x;
    for(int i = threadIdx.x; i < 3456; i += 128) swt[i] = sw[i];
    sbias[threadIdx.x] = sb[threadIdx.x];
    float mv[27];
    #pragma unroll
    for(int m = 0; m < 3; m++)
        #pragma unroll
        for(int ky = 0; ky < 3; ky++)
            #pragma unroll
            for(int kx = 0; kx < 3; kx++){
                int gy = y + ky - 1, gx = x + kx - 1;
                mv[m*9 + ky*3 + kx] = (gy >= 0 && gy < 128 && gx >= 0 && gx < 128)
                    ? mask[((size_t)(b*3+m)<<14) + (gy<<7) + gx] : 0.f;
            }
    __syncthreads();
    unsigned outp[64];
    for(int icp = 0; icp < 64; icp++){
        float a0 = sbias[2*icp], a1 = sbias[2*icp+1];
        const float* w0 = &swt[(2*icp)*27];
        const float* w1 = w0 + 27;
        #pragma unroll
        for(int k = 0; k < 27; k++){ a0 += mv[k]*w0[k]; a1 += mv[k]*w1[k]; }
        __nv_bfloat162 h = __floats2bfloat162_rn(fmaxf(a0, 0.f), fmaxf(a1, 0.f));
        outp[icp] = *reinterpret_cast<unsigned*>(&h);
    }
    uint4* dst = reinterpret_cast<uint4*>(g_actvB) + ((size_t)((b<<14) + (y<<7) + x))*16;
    const uint4* srcp = reinterpret_cast<const uint4*>(outp);
    #pragma unroll
    for(int i = 0; i < 16; i++) dst[i] = srcp[i];
}

// ---------------- K7: SPADE conv via mma.sync bf16 (one block per (b, image row)) ----------------
// dyn smem: sA[3][130][136] bf16 (halo rows, px index = real px + 1, borders zero)
//           sW[2][128][136] bf16 (per-tap weight tile, double-buffered)
#define APLANE 17680             // 130*136 elems
#define WBUF   17408             // 128*136 elems
#define SPADE_SMEM ((3*APLANE + 2*WBUF)*2)

__global__ void __launch_bounds__(256) spade_mma_kernel(const float* __restrict__ gbias,
                                                        const float* __restrict__ bbias){
    extern __shared__ __align__(16) unsigned char dynsm[];
    __nv_bfloat16* sA = reinterpret_cast<__nv_bfloat16*>(dynsm);
    __nv_bfloat16* sW = sA + 3*APLANE;
    __shared__ float s_bias[128];

    int y = blockIdx.x, b = blockIdx.y;
    int tid = threadIdx.x;
    if(tid < 128) s_bias[tid] = (tid < 64) ? gbias[tid] : bbias[tid-64];

    // --- stage A halo rows + zero borders/OOB planes ---
    for(int dy = 0; dy < 3; dy++){
        int sr = y + dy - 1;
        uint4* plane4 = reinterpret_cast<uint4*>(sA + dy*APLANE);
        if(sr < 0 || sr > 127){
            for(int i = tid; i < 2210; i += 256) plane4[i] = make_uint4(0,0,0,0);
        }else{
            if(tid < 17) plane4[tid] = make_uint4(0,0,0,0);                    // px 0 row
            else if(tid < 34) plane4[129*17 + (tid-17)] = make_uint4(0,0,0,0); // px 129 row
            const __nv_bfloat16* src = g_actvB + ((size_t)((b<<14) + (sr<<7)))*128;
            for(int i = tid; i < 2048; i += 256){
                int px = i >> 4, ch = i & 15;
                unsigned dst = smem_u32(sA + dy*APLANE + (px+1)*136 + ch*8);
                cpa16(dst, src + px*128 + ch*8);
            }
        }
    }
    // --- prefetch W tap 0 ---
    {
        const __nv_bfloat16* src = g_wBp;
        for(int i = tid; i < 2048; i += 256){
            int n = i >> 4, ch = i & 15;
            cpa16(smem_u32(sW + n*136 + ch*8), src + n*128 + ch*8);
        }
    }
    CPA_COMMIT();
    CPA_WAIT0();
    __syncthreads();

    int lane = tid & 31, warp = tid >> 5;
    int wM = warp & 3, wN = warp >> 2;
    unsigned sA_u = smem_u32(sA);
    unsigned sW_u = smem_u32(sW);

    float d[2][8][4];
    #pragma unroll
    for(int mt=0; mt<2; mt++)
        #pragma unroll
        for(int nt=0; nt<8; nt++)
            #pragma unroll
            for(int e=0; e<4; e++) d[mt][nt][e] = 0.f;

    int aRow = (lane & 15);            // ldmatrix row supplier
    int aHalf = (lane >> 4);           // 0/1 -> k halves
    int bN = lane & 7;                 // B row supplier (lanes 0..15 used)
    int bHalf = (lane >> 3) & 1;

    for(int tap = 0; tap < 9; tap++){
        if(tap < 8){
            const __nv_bfloat16* src = g_wBp + (tap+1)*16384;
            __nv_bfloat16* dstb = sW + ((tap+1) & 1)*WBUF;
            for(int i = tid; i < 2048; i += 256){
                int n = i >> 4, ch = i & 15;
                cpa16(smem_u32(dstb + n*136 + ch*8), src + n*128 + ch*8);
            }
            CPA_COMMIT();
        }
        int dy = tap/3, dx = tap%3;
        unsigned aBase = sA_u + (unsigned)(dy*APLANE)*2;
        unsigned wBase = sW_u + (unsigned)((tap & 1)*WBUF)*2;
        #pragma unroll
        for(int ks = 0; ks < 8; ks++){
            unsigned a[2][4];
            #pragma unroll
            for(int mt = 0; mt < 2; mt++){
                unsigned ad = aBase + (unsigned)(((wM*32 + mt*16 + aRow + dx)*136
                                 + ks*16 + aHalf*8) << 1);
                ldmx4(a[mt], ad);
            }
            unsigned bq[8][2];
            #pragma unroll
            for(int nt = 0; nt < 8; nt++){
                unsigned bd = wBase + (unsigned)(((wN*64 + nt*8 + bN)*136
                                 + ks*16 + bHalf*8) << 1);
                ldmx2(bq[nt], bd);
            }
            #pragma unroll
            for(int mt = 0; mt < 2; mt++)
                #pragma unroll
                for(int nt = 0; nt < 8; nt++)
                    mma16816(d[mt][nt], a[mt], bq[nt]);
        }
        CPA_WAIT0();
        __syncthreads();
    }

    // --- epilogue: D[px][oc] -> g_spg/g_spb (+bias) ---
    #pragma unroll
    for(int mt = 0; mt < 2; mt++){
        int px = wM*32 + mt*16 + (lane >> 2);
        #pragma unroll
        for(int nt = 0; nt < 8; nt++){
            int oc = wN*64 + nt*8 + (lane & 3)*2;
            #pragma unroll
            for(int e = 0; e < 4; e++){
                int p = px + (e >> 1)*8;
                int o = oc + (e & 1);
                float v = d[mt][nt][e] + s_bias[o];
                if(o < 64) g_spg[((size_t)(b*64 + o)<<14) + (y<<7) + p] = v;
                else       g_spb[((size_t)(b*64 + o - 64)<<14) + (y<<7) + p] = v;
            }
        }
    }
}

// ---------------- K8: fused region-gather + instance-norm + blend ----------------
__global__ void __launch_bounds__(128) final_kernel(const float* __restrict__ x,
        const float* __restrict__ nvar, const float* __restrict__ cgb,
        const float* __restrict__ cbb, const float* __restrict__ bg,
        const float* __restrict__ bb2, float* __restrict__ out){
    __shared__ __align__(16) float sGg[7*584];
    __shared__ __align__(16) float sGb[7*584];
    __shared__ float s_mean[64], s_rstd[64], s_nv[64], s_gb[64], s_bb[64];
    int b = blockIdx.y, y = blockIdx.x, tidx = threadIdx.x;
    for(int i = tidx; i < 7*584; i += 128){
        int r = i/584, k = i%584;
        float vg = 0.f, vb = 0.f;
        if(r < 6 && k < 576){ vg = g_Gg[(b*6+r)*576 + k]; vb = g_Gb[(b*6+r)*576 + k]; }
        sGg[i] = vg; sGb[i] = vb;
    }
    if(tidx < 64){
        s_mean[tidx] = g_mean[b*64+tidx]; s_rstd[tidx] = g_rstd[b*64+tidx];
        s_nv[tidx] = nvar[tidx]; s_gb[tidx] = cgb[tidx]; s_bb[tidx] = cbb[tidx];
    }
    __syncthreads();
    float ga = 1.f/(1.f + expf(-bg[0]));
    float ba = 1.f/(1.f + expf(-bb2[0]));
    int xcol = tidx;
    int base[9];
    #pragma unroll
    for(int tap = 0; tap < 9; tap++){
        int dy = tap/3 - 1, dx = tap%3 - 1;
        int yy = y + dy, xx = xcol + dx;
        int r = 6;
        if(yy >= 0 && yy < 128 && xx >= 0 && xx < 128) r = g_region[(b<<14) + (yy<<7) + xx];
        base[tap] = r*584 + tap*64;
    }
    float nz = g_noiseT[(b<<14) + (y<<7) + xcol];
    size_t pix = (size_t)(y<<7) + xcol;
    for(int j = 0; j < 16; j++){
        unsigned long long ag0=0ull, ag1=0ull, ab0=0ull, ab1=0ull;
        #pragma unroll
        for(int tap = 0; tap < 9; tap++){
            const ulonglong2* pgp = reinterpret_cast<const ulonglong2*>(&sGg[base[tap] + j*4]);
            const ulonglong2* pbp = reinterpret_cast<const ulonglong2*>(&sGb[base[tap] + j*4]);
            ulonglong2 vg = *pgp, vb = *pbp;
            add2(ag0, vg.x); add2(ag1, vg.y);
            add2(ab0, vb.x); add2(ab1, vb.y);
        }
        float g4[4], b4[4];
        upk2(ag0, g4[0], g4[1]); upk2(ag1, g4[2], g4[3]);
        upk2(ab0, b4[0], b4[1]); upk2(ab1, b4[2], b4[3]);
        #pragma unroll
        for(int k = 0; k < 4; k++){
            int c = j*4 + k;
            size_t idx = (((size_t)(b*64 + c))<<14) + pix;
            float xv = x[idx] + s_nv[c]*nz;
            float xn = (xv - s_mean[c])*s_rstd[c];
            float gf = ga*(g4[k] + s_gb[c]) + (1.f - ga)*g_spg[idx];
            float bf = ba*(b4[k] + s_bb[c]) + (1.f - ba)*g_spb[idx];
            out[idx] = xn*(1.f + gf) + bf;
        }
    }
}

extern "C" void kernel_launch(void* const* d_in, const int* in_sizes, int n_in,
                              void* d_out, int out_size) {
    const float* x      = (const float*)d_in[0];
    const float* segmap = (const float*)d_in[1];
    const float* mask   = (const float*)d_in[2];
    const float* codes  = (const float*)d_in[3];
    const float* noise  = (const float*)d_in[4];
    const float* nvar   = (const float*)d_in[5];
    const float* fc_w   = (const float*)d_in[6];
    const float* fc_b   = (const float*)d_in[7];
    const float* cg_w   = (const float*)d_in[8];
    const float* cg_b   = (const float*)d_in[9];
    const float* cb_w   = (const float*)d_in[10];
    const float* cb_b   = (const float*)d_in[11];
    const float* ss_w   = (const float*)d_in[12];
    const float* ss_b   = (const float*)d_in[13];
    const float* sg_w   = (const float*)d_in[14];
    const float* sg_b   = (const float*)d_in[15];
    const float* sb_w   = (const float*)d_in[16];
    const float* sb_b   = (const float*)d_in[17];
    const float* bgam   = (const float*)d_in[18];
    const float* bbet   = (const float*)d_in[19];
    float* out = (float*)d_out;

    cudaFuncSetAttribute(spade_mma_kernel,
                         cudaFuncAttributeMaxDynamicSharedMemorySize, SPADE_SMEM);

    noiseT_kernel<<<256, 256>>>(noise);
    stats_kernel<<<256, 256>>>(x, nvar);
    mmu_kernel<<<24, 256>>>(codes, fc_w, fc_b);
    cwt_kernel<<<2304, 256>>>(cg_w, cb_w);
    gtab_kernel<<<dim3(24,16), 256>>>();
    region_kernel<<<256, 256>>>(segmap);
    wtrans_kernel<<<576, 256>>>(sg_w, sb_w);
    actv_kernel<<<dim3(128,4), 128>>>(mask, ss_w, ss_b);
    spade_mma_kernel<<<dim3(128,4), 256, SPADE_SMEM>>>(sg_b, sb_b);
    final_kernel<<<dim3(128,4), 128>>>(x, nvar, cg_b, cb_b, bgam, bbet, out);
}

// round 7
// speedup vs baseline: 2.7924x; 1.0547x over previous
#include <cuda_runtime.h>
#include <cuda_bf16.h>
#include <math.h>

#define HW_ 16384

// ---------------- scratch (static device globals; no allocation) ----------------
__device__ __nv_bfloat16 g_actvB[4*HW_*128];   // NHWC bf16: [b][y][x][ic]
__device__ __nv_bfloat16 g_wBp[9*128*128];     // [tap][oc][ic] bf16
__device__ float g_noiseT[4*HW_];
__device__ float g_mean[256];
__device__ float g_rstd[256];
__device__ float g_mmu[4*6*512];
__device__ float g_Gg[4*6*576];
__device__ float g_Gb[4*6*576];
__device__ unsigned char g_region[4*HW_];

// ---------------- f32x2 helpers ----------------
__device__ __forceinline__ void upk2(unsigned long long v, float& a, float& b){
    asm("mov.b64 {%0,%1}, %2;" : "=f"(a), "=f"(b) : "l"(v));
}
__device__ __forceinline__ void add2(unsigned long long& d, unsigned long long a){
    asm("add.rn.f32x2 %0, %1, %2;" : "=l"(d) : "l"(a), "l"(d));
}

// ---------------- mma / ldmatrix / cp.async helpers (sm_80+ portable) ----------------
__device__ __forceinline__ unsigned smem_u32(const void* p){
    unsigned r; asm("{ .reg .u64 t; cvta.to.shared.u64 t, %1; cvt.u32.u64 %0, t; }" : "=r"(r) : "l"(p));
    return r;
}
__device__ __forceinline__ void ldmx4(unsigned* r, unsigned addr){
    asm volatile("ldmatrix.sync.aligned.m8n8.x4.shared.b16 {%0,%1,%2,%3}, [%4];"
        : "=r"(r[0]),"=r"(r[1]),"=r"(r[2]),"=r"(r[3]) : "r"(addr));
}
__device__ __forceinline__ void ldmx2(unsigned* r, unsigned addr){
    asm volatile("ldmatrix.sync.aligned.m8n8.x2.shared.b16 {%0,%1}, [%2];"
        : "=r"(r[0]),"=r"(r[1]) : "r"(addr));
}
__device__ __forceinline__ void mma16816(float* d, const unsigned* a, const unsigned* bq){
    asm volatile("mma.sync.aligned.m16n8k16.row.col.f32.bf16.bf16.f32 "
        "{%0,%1,%2,%3}, {%4,%5,%6,%7}, {%8,%9}, {%0,%1,%2,%3};"
        : "+f"(d[0]),"+f"(d[1]),"+f"(d[2]),"+f"(d[3])
        : "r"(a[0]),"r"(a[1]),"r"(a[2]),"r"(a[3]), "r"(bq[0]),"r"(bq[1]));
}
__device__ __forceinline__ void cpa16(unsigned dst, const void* src){
    asm volatile("cp.async.cg.shared.global [%0], [%1], 16;" :: "r"(dst), "l"(src) : "memory");
}
#define CPA_COMMIT() asm volatile("cp.async.commit_group;" ::: "memory")
#define CPA_WAIT0()  asm volatile("cp.async.wait_group 0;" ::: "memory")

// ---------------- K0: noise (B,W,H,1) -> [b][h][w] ----------------
__global__ void noiseT_kernel(const float* __restrict__ noise){
    int i = blockIdx.x*256 + threadIdx.x;
    int b = i >> 14, p = i & 16383;
    int h = p >> 7, w = p & 127;
    g_noiseT[i] = noise[(b<<14) + (w<<7) + h];
}

// ---------------- K1: instance-norm stats ----------------
__global__ void stats_kernel(const float* __restrict__ x, const float* __restrict__ nvar){
    int bc = blockIdx.x; int b = bc >> 6, c = bc & 63;
    float nv = nvar[c];
    const float4* xp = reinterpret_cast<const float4*>(x + (size_t)bc*HW_);
    const float4* np = reinterpret_cast<const float4*>(g_noiseT + (size_t)b*HW_);
    float s = 0.f, ss = 0.f;
    for(int i = threadIdx.x; i < HW_/4; i += 256){
        float4 xv = xp[i]; float4 nn = np[i];
        float v;
        v = xv.x + nv*nn.x; s += v; ss += v*v;
        v = xv.y + nv*nn.y; s += v; ss += v*v;
        v = xv.z + nv*nn.z; s += v; ss += v*v;
        v = xv.w + nv*nn.w; s += v; ss += v*v;
    }
    __shared__ float rs[256], rq[256];
    rs[threadIdx.x] = s; rq[threadIdx.x] = ss;
    __syncthreads();
    for(int st = 128; st > 0; st >>= 1){
        if(threadIdx.x < st){ rs[threadIdx.x] += rs[threadIdx.x+st]; rq[threadIdx.x] += rq[threadIdx.x+st]; }
        __syncthreads();
    }
    if(threadIdx.x == 0){
        float m = rs[0]*(1.f/HW_);
        float var = rq[0]*(1.f/HW_) - m*m;
        g_mean[bc] = m;
        g_rstd[bc] = rsqrtf(var + 1e-5f);
    }
}

// ---------------- K2: middle_mu ----------------
__global__ void __launch_bounds__(256) mmu_kernel(const float* __restrict__ codes,
                                                  const float* __restrict__ fcw,
                                                  const float* __restrict__ fcb){
    int bf = blockIdx.x; int f = bf % 6;
    int lane = threadIdx.x & 31, warp = threadIdx.x >> 5;
    float c[16];
    const float4* cp = reinterpret_cast<const float4*>(codes + (size_t)bf*512);
    #pragma unroll
    for(int it=0; it<4; it++){
        float4 v = cp[it*32 + lane];
        c[it*4+0]=v.x; c[it*4+1]=v.y; c[it*4+2]=v.z; c[it*4+3]=v.w;
    }
    for(int o = warp; o < 512; o += 8){
        const float4* wp = reinterpret_cast<const float4*>(fcw + ((size_t)f*512 + o)*512);
        float s = 0.f;
        #pragma unroll
        for(int it=0; it<4; it++){
            float4 w = wp[it*32 + lane];
            s += w.x*c[it*4] + w.y*c[it*4+1] + w.z*c[it*4+2] + w.w*c[it*4+3];
        }
        #pragma unroll
        for(int st=16; st>0; st>>=1) s += __shfl_xor_sync(0xffffffffu, s, st);
        if(lane==0) g_mmu[bf*512+o] = fmaxf(s + fcb[f*512+o], 0.f);
    }
}

// ---------------- K3: fused G tables (one block per (table, oc)) ----------------
// dyn smem: sw[4608] (w[oc,:,:] row) + sm[12288] (all mmu) = 67584 B
#define GTAB_SMEM ((4608 + 12288)*4)
__global__ void __launch_bounds__(256) gtab2_kernel(const float* __restrict__ wg,
                                                    const float* __restrict__ wb){
    extern __shared__ float gsm[];
    float* sw = gsm;             // [d*9 + tap]
    float* sm = gsm + 4608;      // [bf*512 + d]
    int blk = blockIdx.x;        // 0..127
    int table = blk >> 6, oc = blk & 63;
    int tid = threadIdx.x;
    const float* w = (table ? wb : wg) + (size_t)oc*4608;
    for(int i = tid; i < 4608; i += 256) sw[i] = w[i];
    for(int i = tid; i < 12288; i += 256) sm[i] = g_mmu[i];
    __syncthreads();
    if(tid < 216){
        int bf = tid / 9, tap = tid % 9;
        const float* mrow = &sm[bf*512];
        float s0=0.f, s1=0.f, s2=0.f, s3=0.f;
        #pragma unroll 4
        for(int d = 0; d < 512; d += 4){
            s0 += sw[d*9 + tap]       * mrow[d];
            s1 += sw[(d+1)*9 + tap]   * mrow[d+1];
            s2 += sw[(d+2)*9 + tap]   * mrow[d+2];
            s3 += sw[(d+3)*9 + tap]   * mrow[d+3];
        }
        float s = (s0+s1) + (s2+s3);
        if(table) g_Gb[bf*576 + tap*64 + oc] = s;
        else      g_Gg[bf*576 + tap*64 + oc] = s;
    }
}

// ---------------- K4: region map ----------------
__global__ void region_kernel(const float* __restrict__ segmap){
    int i = blockIdx.x*256 + threadIdx.x;
    int b = i >> 14, p = i & 16383;
    unsigned char r = 6;
    #pragma unroll
    for(int j = 0; j < 6; j++)
        if(segmap[((size_t)(b*6+j)<<14) + p] != 0.f) r = (unsigned char)j;
    g_region[i] = r;
}

// ---------------- K5: spade weights -> [tap][oc][ic] bf16 ----------------
__global__ void wtrans_kernel(const float* __restrict__ wg, const float* __restrict__ wb){
    int i = blockIdx.x*256 + threadIdx.x;            // 147456
    int tap = i >> 14; int oc = (i >> 7) & 127; int ic = i & 127;
    float v = (oc < 64) ? wg[(size_t)oc*1152 + ic*9 + tap]
                        : wb[(size_t)(oc-64)*1152 + ic*9 + tap];
    g_wBp[i] = __float2bfloat16(v);
}

// ---------------- K6: actv = relu(conv3x3(mask 3->128)) -> NHWC bf16 ----------------
__global__ void __launch_bounds__(128) actv_kernel(const float* __restrict__ mask,
                                                   const float* __restrict__ sw,
                                                   const float* __restrict__ sb){
    __shared__ float swt[3456];
    __shared__ float sbias[128];
    int y = blockIdx.x, b = blockIdx.y, x = threadIdx.x;
    for(int i = threadIdx.x; i < 3456; i += 128) swt[i] = sw[i];
    sbias[threadIdx.x] = sb[threadIdx.x];
    float mv[27];
    #pragma unroll
    for(int m = 0; m < 3; m++)
        #pragma unroll
        for(int ky = 0; ky < 3; ky++)
            #pragma unroll
            for(int kx = 0; kx < 3; kx++){
                int gy = y + ky - 1, gx = x + kx - 1;
                mv[m*9 + ky*3 + kx] = (gy >= 0 && gy < 128 && gx >= 0 && gx < 128)
                    ? mask[((size_t)(b*3+m)<<14) + (gy<<7) + gx] : 0.f;
            }
    __syncthreads();
    unsigned outp[64];
    for(int icp = 0; icp < 64; icp++){
        float a0 = sbias[2*icp], a1 = sbias[2*icp+1];
        const float* w0 = &swt[(2*icp)*27];
        const float* w1 = w0 + 27;
        #pragma unroll
        for(int k = 0; k < 27; k++){ a0 += mv[k]*w0[k]; a1 += mv[k]*w1[k]; }
        __nv_bfloat162 h = __floats2bfloat162_rn(fmaxf(a0, 0.f), fmaxf(a1, 0.f));
        outp[icp] = *reinterpret_cast<unsigned*>(&h);
    }
    uint4* dst = reinterpret_cast<uint4*>(g_actvB) + ((size_t)((b<<14) + (y<<7) + x))*16;
    const uint4* srcp = reinterpret_cast<const uint4*>(outp);
    #pragma unroll
    for(int i = 0; i < 16; i++) dst[i] = srcp[i];
}

// ---------------- K7: SPADE conv (mma.sync bf16) + FUSED final epilogue ----------------
// dyn smem: sA[3][130][136] bf16 halo planes; sW[2][128][136] bf16 double-buffered weights
// after MMAs: sA region reused as Dsm[128][129] fp32; sW region reused as G tables
#define APLANE 17680             // 130*136 elems
#define WBUF   17408             // 128*136 elems
#define SPADE_SMEM ((3*APLANE + 2*WBUF)*2)

__global__ void __launch_bounds__(256) spade_fused_kernel(
        const float* __restrict__ x,   const float* __restrict__ nvar,
        const float* __restrict__ sgb, const float* __restrict__ sbb,
        const float* __restrict__ cgb, const float* __restrict__ cbb,
        const float* __restrict__ bg,  const float* __restrict__ bb2,
        float* __restrict__ out){
    extern __shared__ __align__(16) unsigned char dynsm[];
    __nv_bfloat16* sA = reinterpret_cast<__nv_bfloat16*>(dynsm);
    __nv_bfloat16* sW = sA + 3*APLANE;
    __shared__ float s_bias[128];
    __shared__ float s_mean[64], s_rstd[64], s_nv[64], s_gb[64], s_bb[64];

    int y = blockIdx.x, b = blockIdx.y;
    int tid = threadIdx.x;
    if(tid < 128) s_bias[tid] = (tid < 64) ? sgb[tid] : sbb[tid-64];
    else{
        int t = tid - 128;
        if(t < 64){
            s_mean[t] = g_mean[b*64+t]; s_rstd[t] = g_rstd[b*64+t];
            s_nv[t] = nvar[t]; s_gb[t] = cgb[t]; s_bb[t] = cbb[t];
        }
    }

    // --- stage A halo rows + zero borders/OOB planes ---
    for(int dy = 0; dy < 3; dy++){
        int sr = y + dy - 1;
        uint4* plane4 = reinterpret_cast<uint4*>(sA + dy*APLANE);
        if(sr < 0 || sr > 127){
            for(int i = tid; i < 2210; i += 256) plane4[i] = make_uint4(0,0,0,0);
        }else{
            if(tid < 17) plane4[tid] = make_uint4(0,0,0,0);                    // px -1
            else if(tid < 34) plane4[129*17 + (tid-17)] = make_uint4(0,0,0,0); // px 128
            const __nv_bfloat16* src = g_actvB + ((size_t)((b<<14) + (sr<<7)))*128;
            for(int i = tid; i < 2048; i += 256){
                int px = i >> 4, ch = i & 15;
                cpa16(smem_u32(sA + dy*APLANE + (px+1)*136 + ch*8), src + px*128 + ch*8);
            }
        }
    }
    // --- prefetch W tap 0 ---
    for(int i = tid; i < 2048; i += 256){
        int n = i >> 4, ch = i & 15;
        cpa16(smem_u32(sW + n*136 + ch*8), g_wBp + n*128 + ch*8);
    }
    CPA_COMMIT();
    CPA_WAIT0();
    __syncthreads();

    int lane = tid & 31, warp = tid >> 5;
    int wM = warp & 3, wN = warp >> 2;
    unsigned sA_u = smem_u32(sA);
    unsigned sW_u = smem_u32(sW);

    float d[2][8][4];
    #pragma unroll
    for(int mt=0; mt<2; mt++)
        #pragma unroll
        for(int nt=0; nt<8; nt++)
            #pragma unroll
            for(int e=0; e<4; e++) d[mt][nt][e] = 0.f;

    int aRow = (lane & 15);
    int aHalf = (lane >> 4);
    int bN = lane & 7;
    int bHalf = (lane >> 3) & 1;

    for(int tap = 0; tap < 9; tap++){
        if(tap < 8){
            const __nv_bfloat16* src = g_wBp + (tap+1)*16384;
            __nv_bfloat16* dstb = sW + ((tap+1) & 1)*WBUF;
            for(int i = tid; i < 2048; i += 256){
                int n = i >> 4, ch = i & 15;
                cpa16(smem_u32(dstb + n*136 + ch*8), src + n*128 + ch*8);
            }
            CPA_COMMIT();
        }
        int dy = tap/3, dx = tap%3;
        unsigned aBase = sA_u + (unsigned)(dy*APLANE)*2;
        unsigned wBase = sW_u + (unsigned)((tap & 1)*WBUF)*2;
        #pragma unroll
        for(int ks = 0; ks < 8; ks++){
            unsigned a[2][4];
            #pragma unroll
            for(int mt = 0; mt < 2; mt++){
                unsigned ad = aBase + (unsigned)(((wM*32 + mt*16 + aRow + dx)*136
                                 + ks*16 + aHalf*8) << 1);
                ldmx4(a[mt], ad);
            }
            unsigned bq[8][2];
            #pragma unroll
            for(int nt = 0; nt < 8; nt++){
                unsigned bd = wBase + (unsigned)(((wN*64 + nt*8 + bN)*136
                                 + ks*16 + bHalf*8) << 1);
                ldmx2(bq[nt], bd);
            }
            #pragma unroll
            for(int mt = 0; mt < 2; mt++)
                #pragma unroll
                for(int nt = 0; nt < 8; nt++)
                    mma16816(d[mt][nt], a[mt], bq[nt]);
        }
        CPA_WAIT0();
        __syncthreads();
    }

    // --- dump D (+spade bias) into smem (reuse A region), pitch 129 ---
    float* Dsm = reinterpret_cast<float*>(sA);
    #pragma unroll
    for(int mt = 0; mt < 2; mt++){
        int px = wM*32 + mt*16 + (lane >> 2);
        #pragma unroll
        for(int nt = 0; nt < 8; nt++){
            int oc = wN*64 + nt*8 + (lane & 3)*2;
            #pragma unroll
            for(int e = 0; e < 4; e++){
                int p = px + (e >> 1)*8;
                int o = oc + (e & 1);
                Dsm[p*129 + o] = d[mt][nt][e] + s_bias[o];
            }
        }
    }
    // --- load G tables into smem (reuse W region) ---
    float* tGg = reinterpret_cast<float*>(sW);
    float* tGb = tGg + 7*584;
    for(int i = tid; i < 7*584; i += 256){
        int r = i/584, k = i%584;
        float vg = 0.f, vb = 0.f;
        if(r < 6 && k < 576){ vg = g_Gg[(b*6+r)*576 + k]; vb = g_Gb[(b*6+r)*576 + k]; }
        tGg[i] = vg; tGb[i] = vb;
    }
    __syncthreads();

    // --- fused final: 256 threads = 128 px x 2 channel-halves ---
    float ga = 1.f/(1.f + expf(-bg[0]));
    float ba = 1.f/(1.f + expf(-bb2[0]));
    int px = tid & 127;
    int half = tid >> 7;
    int base[9];
    #pragma unroll
    for(int tap = 0; tap < 9; tap++){
        int dy = tap/3 - 1, dx = tap%3 - 1;
        int yy = y + dy, xx = px + dx;
        int r = 6;
        if(yy >= 0 && yy < 128 && xx >= 0 && xx < 128) r = g_region[(b<<14) + (yy<<7) + xx];
        base[tap] = r*584 + tap*64;
    }
    float nz = g_noiseT[(b<<14) + (y<<7) + px];
    size_t pix = (size_t)(y<<7) + px;
    for(int jj = 0; jj < 8; jj++){
        int j = half*8 + jj;
        unsigned long long ag0=0ull, ag1=0ull, ab0=0ull, ab1=0ull;
        #pragma unroll
        for(int tap = 0; tap < 9; tap++){
            const ulonglong2* pgp = reinterpret_cast<const ulonglong2*>(&tGg[base[tap] + j*4]);
            const ulonglong2* pbp = reinterpret_cast<const ulonglong2*>(&tGb[base[tap] + j*4]);
            ulonglong2 vg = *pgp, vb = *pbp;
            add2(ag0, vg.x); add2(ag1, vg.y);
            add2(ab0, vb.x); add2(ab1, vb.y);
        }
        float g4[4], b4[4];
        upk2(ag0, g4[0], g4[1]); upk2(ag1, g4[2], g4[3]);
        upk2(ab0, b4[0], b4[1]); upk2(ab1, b4[2], b4[3]);
        #pragma unroll
        for(int k = 0; k < 4; k++){
            int c = j*4 + k;
            size_t idx = (((size_t)(b*64 + c))<<14) + pix;
            float xv = x[idx] + s_nv[c]*nz;
            float xn = (xv - s_mean[c])*s_rstd[c];
            float gf = ga*(g4[k] + s_gb[c]) + (1.f - ga)*Dsm[px*129 + c];
            float bf = ba*(b4[k] + s_bb[c]) + (1.f - ba)*Dsm[px*129 + 64 + c];
            out[idx] = xn*(1.f + gf) + bf;
        }
    }
}

extern "C" void kernel_launch(void* const* d_in, const int* in_sizes, int n_in,
                              void* d_out, int out_size) {
    const float* x      = (const float*)d_in[0];
    const float* segmap = (const float*)d_in[1];
    const float* mask   = (const float*)d_in[2];
    const float* codes  = (const float*)d_in[3];
    const float* noise  = (const float*)d_in[4];
    const float* nvar   = (const float*)d_in[5];
    const float* fc_w   = (const float*)d_in[6];
    const float* fc_b   = (const float*)d_in[7];
    const float* cg_w   = (const float*)d_in[8];
    const float* cg_b   = (const float*)d_in[9];
    const float* cb_w   = (const float*)d_in[10];
    const float* cb_b   = (const float*)d_in[11];
    const float* ss_w   = (const float*)d_in[12];
    const float* ss_b   = (const float*)d_in[13];
    const float* sg_w   = (const float*)d_in[14];
    const float* sg_b   = (const float*)d_in[15];
    const float* sb_w   = (const float*)d_in[16];
    const float* sb_b   = (const float*)d_in[17];
    const float* bgam   = (const float*)d_in[18];
    const float* bbet   = (const float*)d_in[19];
    float* out = (float*)d_out;

    cudaFuncSetAttribute(spade_fused_kernel,
                         cudaFuncAttributeMaxDynamicSharedMemorySize, SPADE_SMEM);
    cudaFuncSetAttribute(gtab2_kernel,
                         cudaFuncAttributeMaxDynamicSharedMemorySize, GTAB_SMEM);

    noiseT_kernel<<<256, 256>>>(noise);
    stats_kernel<<<256, 256>>>(x, nvar);
    mmu_kernel<<<24, 256>>>(codes, fc_w, fc_b);
    gtab2_kernel<<<128, 256, GTAB_SMEM>>>(cg_w, cb_w);
    region_kernel<<<256, 256>>>(segmap);
    wtrans_kernel<<<576, 256>>>(sg_w, sb_w);
    actv_kernel<<<dim3(128,4), 128>>>(mask, ss_w, ss_b);
    spade_fused_kernel<<<dim3(128,4), 256, SPADE_SMEM>>>(
        x, nvar, sg_b, sb_b, cg_b, cb_b, bgam, bbet, out);
}

// round 8
// speedup vs baseline: 3.0395x; 1.0885x over previous
#include <cuda_runtime.h>
#include <cuda_bf16.h>
#include <math.h>

#define HW_ 16384

// ---------------- scratch (static device globals; no allocation) ----------------
__device__ __nv_bfloat16 g_actvB[4*HW_*128];   // NHWC bf16: [b][y][x][ic]
__device__ __nv_bfloat16 g_wBp[9*128*128];     // [tap][oc][ic] bf16
__device__ float g_mean[256];
__device__ float g_rstd[256];
__device__ float g_mmu[4*6*512];
__device__ float g_Gg[4*6*576];
__device__ float g_Gb[4*6*576];
__device__ unsigned char g_region[4*HW_];

// ---------------- f32x2 helpers ----------------
__device__ __forceinline__ void upk2(unsigned long long v, float& a, float& b){
    asm("mov.b64 {%0,%1}, %2;" : "=f"(a), "=f"(b) : "l"(v));
}
__device__ __forceinline__ void add2(unsigned long long& d, unsigned long long a){
    asm("add.rn.f32x2 %0, %1, %2;" : "=l"(d) : "l"(a), "l"(d));
}

// ---------------- mma / ldmatrix / cp.async helpers (sm_80+ portable) ----------------
__device__ __forceinline__ unsigned smem_u32(const void* p){
    unsigned r; asm("{ .reg .u64 t; cvta.to.shared.u64 t, %1; cvt.u32.u64 %0, t; }" : "=r"(r) : "l"(p));
    return r;
}
__device__ __forceinline__ void ldmx4(unsigned* r, unsigned addr){
    asm volatile("ldmatrix.sync.aligned.m8n8.x4.shared.b16 {%0,%1,%2,%3}, [%4];"
        : "=r"(r[0]),"=r"(r[1]),"=r"(r[2]),"=r"(r[3]) : "r"(addr));
}
__device__ __forceinline__ void ldmx2(unsigned* r, unsigned addr){
    asm volatile("ldmatrix.sync.aligned.m8n8.x2.shared.b16 {%0,%1}, [%2];"
        : "=r"(r[0]),"=r"(r[1]) : "r"(addr));
}
__device__ __forceinline__ void mma16816(float* d, const unsigned* a, const unsigned* bq){
    asm volatile("mma.sync.aligned.m16n8k16.row.col.f32.bf16.bf16.f32 "
        "{%0,%1,%2,%3}, {%4,%5,%6,%7}, {%8,%9}, {%0,%1,%2,%3};"
        : "+f"(d[0]),"+f"(d[1]),"+f"(d[2]),"+f"(d[3])
        : "r"(a[0]),"r"(a[1]),"r"(a[2]),"r"(a[3]), "r"(bq[0]),"r"(bq[1]));
}
__device__ __forceinline__ void cpa16(unsigned dst, const void* src){
    asm volatile("cp.async.cg.shared.global [%0], [%1], 16;" :: "r"(dst), "l"(src) : "memory");
}
#define CPA_COMMIT() asm volatile("cp.async.commit_group;" ::: "memory")
#define CPA_WAIT0()  asm volatile("cp.async.wait_group 0;" ::: "memory")

// ---------------- K1: instance-norm stats (noise read transposed in-place) ----------------
__global__ void stats_kernel(const float* __restrict__ x, const float* __restrict__ noise,
                             const float* __restrict__ nvar){
    int bc = blockIdx.x; int b = bc >> 6, c = bc & 63;
    float nv = nvar[c];
    const float4* xp = reinterpret_cast<const float4*>(x + (size_t)bc*HW_);
    const float* nb = noise + (b<<14);
    float s = 0.f, ss = 0.f;
    for(int i = threadIdx.x; i < HW_/4; i += 256){
        float4 xv = xp[i];
        int p4 = i*4;
        int h = p4 >> 7, w0 = p4 & 127;
        // noiseT[h][w] = noise[w][h]
        float n0 = nb[((w0  )<<7) + h];
        float n1 = nb[((w0+1)<<7) + h];
        float n2 = nb[((w0+2)<<7) + h];
        float n3 = nb[((w0+3)<<7) + h];
        float v;
        v = xv.x + nv*n0; s += v; ss += v*v;
        v = xv.y + nv*n1; s += v; ss += v*v;
        v = xv.z + nv*n2; s += v; ss += v*v;
        v = xv.w + nv*n3; s += v; ss += v*v;
    }
    __shared__ float rs[256], rq[256];
    rs[threadIdx.x] = s; rq[threadIdx.x] = ss;
    __syncthreads();
    for(int st = 128; st > 0; st >>= 1){
        if(threadIdx.x < st){ rs[threadIdx.x] += rs[threadIdx.x+st]; rq[threadIdx.x] += rq[threadIdx.x+st]; }
        __syncthreads();
    }
    if(threadIdx.x == 0){
        float m = rs[0]*(1.f/HW_);
        float var = rq[0]*(1.f/HW_) - m*m;
        g_mean[bc] = m;
        g_rstd[bc] = rsqrtf(var + 1e-5f);
    }
}

// ---------------- K2: middle_mu (grid 24 x 8 for occupancy) ----------------
__global__ void __launch_bounds__(256) mmu_kernel(const float* __restrict__ codes,
                                                  const float* __restrict__ fcw,
                                                  const float* __restrict__ fcb){
    int bf = blockIdx.x; int f = bf % 6;
    int og = blockIdx.y;                 // 8 groups of 64 outputs
    int lane = threadIdx.x & 31, warp = threadIdx.x >> 5;
    float c[16];
    const float4* cp = reinterpret_cast<const float4*>(codes + (size_t)bf*512);
    #pragma unroll
    for(int it=0; it<4; it++){
        float4 v = cp[it*32 + lane];
        c[it*4+0]=v.x; c[it*4+1]=v.y; c[it*4+2]=v.z; c[it*4+3]=v.w;
    }
    #pragma unroll
    for(int r = 0; r < 8; r++){
        int o = og*64 + warp*8 + r;
        const float4* wp = reinterpret_cast<const float4*>(fcw + ((size_t)f*512 + o)*512);
        float s = 0.f;
        #pragma unroll
        for(int it=0; it<4; it++){
            float4 w = wp[it*32 + lane];
            s += w.x*c[it*4] + w.y*c[it*4+1] + w.z*c[it*4+2] + w.w*c[it*4+3];
        }
        #pragma unroll
        for(int st=16; st>0; st>>=1) s += __shfl_xor_sync(0xffffffffu, s, st);
        if(lane==0) g_mmu[bf*512+o] = fmaxf(s + fcb[f*512+o], 0.f);
    }
}

// ---------------- K3: G tables, warp-parallel (one block per (table, oc)) ----------------
#define GTAB_SMEM ((4608 + 12288)*4)
__global__ void __launch_bounds__(256) gtab2_kernel(const float* __restrict__ wg,
                                                    const float* __restrict__ wb){
    extern __shared__ float gsm[];
    float* sw = gsm;             // [d*9 + tap]
    float* sm = gsm + 4608;      // [bf*512 + d]
    int blk = blockIdx.x;        // 0..127
    int table = blk >> 6, oc = blk & 63;
    int tid = threadIdx.x;
    int lane = tid & 31, warp = tid >> 5;
    const float* w = (table ? wb : wg) + (size_t)oc*4608;
    for(int i = tid; i < 4608; i += 256) sw[i] = w[i];
    for(int i = tid; i < 12288; i += 256) sm[i] = g_mmu[i];
    __syncthreads();
    // 216 jobs = 8 warps x 27; job -> (bf, tap); lane-split reduce over d
    for(int j = warp*27; j < warp*27 + 27; j++){
        int bf = j / 9, tap = j % 9;
        const float* mrow = &sm[bf*512];
        float acc = 0.f;
        #pragma unroll
        for(int k = 0; k < 16; k++){
            int d = lane + k*32;
            acc += sw[d*9 + tap] * mrow[d];
        }
        #pragma unroll
        for(int st=16; st>0; st>>=1) acc += __shfl_xor_sync(0xffffffffu, acc, st);
        if(lane == 0){
            if(table) g_Gb[bf*576 + tap*64 + oc] = acc;
            else      g_Gg[bf*576 + tap*64 + oc] = acc;
        }
    }
}

// ---------------- K4: prep = wtrans (blocks 0..575) + region (blocks 576..831) ----------------
__global__ void prep_kernel(const float* __restrict__ wg, const float* __restrict__ wb,
                            const float* __restrict__ segmap){
    int blk = blockIdx.x;
    if(blk < 576){
        int i = blk*256 + threadIdx.x;               // 147456: [tap][oc][ic]
        int tap = i >> 14; int oc = (i >> 7) & 127; int ic = i & 127;
        float v = (oc < 64) ? wg[(size_t)oc*1152 + ic*9 + tap]
                            : wb[(size_t)(oc-64)*1152 + ic*9 + tap];
        g_wBp[i] = __float2bfloat16(v);
    }else{
        int i = (blk-576)*256 + threadIdx.x;         // 65536
        int b = i >> 14, p = i & 16383;
        unsigned char r = 6;
        #pragma unroll
        for(int j = 0; j < 6; j++)
            if(segmap[((size_t)(b*6+j)<<14) + p] != 0.f) r = (unsigned char)j;
        g_region[i] = r;
    }
}

// ---------------- K5: actv = relu(conv3x3(mask 3->128)) -> NHWC bf16 ----------------
__global__ void __launch_bounds__(128) actv_kernel(const float* __restrict__ mask,
                                                   const float* __restrict__ sw,
                                                   const float* __restrict__ sb){
    __shared__ float swt[3456];
    __shared__ float sbias[128];
    int y = blockIdx.x, b = blockIdx.y, x = threadIdx.x;
    for(int i = threadIdx.x; i < 3456; i += 128) swt[i] = sw[i];
    sbias[threadIdx.x] = sb[threadIdx.x];
    float mv[27];
    #pragma unroll
    for(int m = 0; m < 3; m++)
        #pragma unroll
        for(int ky = 0; ky < 3; ky++)
            #pragma unroll
            for(int kx = 0; kx < 3; kx++){
                int gy = y + ky - 1, gx = x + kx - 1;
                mv[m*9 + ky*3 + kx] = (gy >= 0 && gy < 128 && gx >= 0 && gx < 128)
                    ? mask[((size_t)(b*3+m)<<14) + (gy<<7) + gx] : 0.f;
            }
    __syncthreads();
    unsigned outp[64];
    for(int icp = 0; icp < 64; icp++){
        float a0 = sbias[2*icp], a1 = sbias[2*icp+1];
        const float* w0 = &swt[(2*icp)*27];
        const float* w1 = w0 + 27;
        #pragma unroll
        for(int k = 0; k < 27; k++){ a0 += mv[k]*w0[k]; a1 += mv[k]*w1[k]; }
        __nv_bfloat162 h = __floats2bfloat162_rn(fmaxf(a0, 0.f), fmaxf(a1, 0.f));
        outp[icp] = *reinterpret_cast<unsigned*>(&h);
    }
    uint4* dst = reinterpret_cast<uint4*>(g_actvB) + ((size_t)((b<<14) + (y<<7) + x))*16;
    const uint4* srcp = reinterpret_cast<const uint4*>(outp);
    #pragma unroll
    for(int i = 0; i < 16; i++) dst[i] = srcp[i];
}

// ---------------- K6: SPADE conv (mma.sync bf16) + FUSED final epilogue ----------------
#define APLANE 17680             // 130*136 elems
#define WBUF   17408             // 128*136 elems
#define SPADE_SMEM ((3*APLANE + 2*WBUF)*2)

__global__ void __launch_bounds__(256) spade_fused_kernel(
        const float* __restrict__ x,   const float* __restrict__ noise,
        const float* __restrict__ nvar,
        const float* __restrict__ sgb, const float* __restrict__ sbb,
        const float* __restrict__ cgb, const float* __restrict__ cbb,
        const float* __restrict__ bg,  const float* __restrict__ bb2,
        float* __restrict__ out){
    extern __shared__ __align__(16) unsigned char dynsm[];
    __nv_bfloat16* sA = reinterpret_cast<__nv_bfloat16*>(dynsm);
    __nv_bfloat16* sW = sA + 3*APLANE;
    __shared__ float s_bias[128];
    __shared__ float s_mean[64], s_rstd[64], s_nv[64], s_gb[64], s_bb[64];

    int y = blockIdx.x, b = blockIdx.y;
    int tid = threadIdx.x;
    if(tid < 128) s_bias[tid] = (tid < 64) ? sgb[tid] : sbb[tid-64];
    else{
        int t = tid - 128;
        if(t < 64){
            s_mean[t] = g_mean[b*64+t]; s_rstd[t] = g_rstd[b*64+t];
            s_nv[t] = nvar[t]; s_gb[t] = cgb[t]; s_bb[t] = cbb[t];
        }
    }

    // --- stage A halo rows + zero borders/OOB planes ---
    for(int dy = 0; dy < 3; dy++){
        int sr = y + dy - 1;
        uint4* plane4 = reinterpret_cast<uint4*>(sA + dy*APLANE);
        if(sr < 0 || sr > 127){
            for(int i = tid; i < 2210; i += 256) plane4[i] = make_uint4(0,0,0,0);
        }else{
            if(tid < 17) plane4[tid] = make_uint4(0,0,0,0);                    // px -1
            else if(tid < 34) plane4[129*17 + (tid-17)] = make_uint4(0,0,0,0); // px 128
            const __nv_bfloat16* src = g_actvB + ((size_t)((b<<14) + (sr<<7)))*128;
            for(int i = tid; i < 2048; i += 256){
                int px = i >> 4, ch = i & 15;
                cpa16(smem_u32(sA + dy*APLANE + (px+1)*136 + ch*8), src + px*128 + ch*8);
            }
        }
    }
    // --- prefetch W tap 0 ---
    for(int i = tid; i < 2048; i += 256){
        int n = i >> 4, ch = i & 15;
        cpa16(smem_u32(sW + n*136 + ch*8), g_wBp + n*128 + ch*8);
    }
    CPA_COMMIT();
    CPA_WAIT0();
    __syncthreads();

    int lane = tid & 31, warp = tid >> 5;
    int wM = warp & 3, wN = warp >> 2;
    unsigned sA_u = smem_u32(sA);
    unsigned sW_u = smem_u32(sW);

    float d[2][8][4];
    #pragma unroll
    for(int mt=0; mt<2; mt++)
        #pragma unroll
        for(int nt=0; nt<8; nt++)
            #pragma unroll
            for(int e=0; e<4; e++) d[mt][nt][e] = 0.f;

    int aRow = (lane & 15);
    int aHalf = (lane >> 4);
    int bN = lane & 7;
    int bHalf = (lane >> 3) & 1;

    for(int tap = 0; tap < 9; tap++){
        if(tap < 8){
            const __nv_bfloat16* src = g_wBp + (tap+1)*16384;
            __nv_bfloat16* dstb = sW + ((tap+1) & 1)*WBUF;
            for(int i = tid; i < 2048; i += 256){
                int n = i >> 4, ch = i & 15;
                cpa16(smem_u32(dstb + n*136 + ch*8), src + n*128 + ch*8);
            }
            CPA_COMMIT();
        }
        int dy = tap/3, dx = tap%3;
        unsigned aBase = sA_u + (unsigned)(dy*APLANE)*2;
        unsigned wBase = sW_u + (unsigned)((tap & 1)*WBUF)*2;
        #pragma unroll
        for(int ks = 0; ks < 8; ks++){
            unsigned a[2][4];
            #pragma unroll
            for(int mt = 0; mt < 2; mt++){
                unsigned ad = aBase + (unsigned)(((wM*32 + mt*16 + aRow + dx)*136
                                 + ks*16 + aHalf*8) << 1);
                ldmx4(a[mt], ad);
            }
            unsigned bq[8][2];
            #pragma unroll
            for(int nt = 0; nt < 8; nt++){
                unsigned bd = wBase + (unsigned)(((wN*64 + nt*8 + bN)*136
                                 + ks*16 + bHalf*8) << 1);
                ldmx2(bq[nt], bd);
            }
            #pragma unroll
            for(int mt = 0; mt < 2; mt++)
                #pragma unroll
                for(int nt = 0; nt < 8; nt++)
                    mma16816(d[mt][nt], a[mt], bq[nt]);
        }
        CPA_WAIT0();
        __syncthreads();
    }

    // --- dump D (+spade bias) into smem (reuse A region), pitch 129 ---
    float* Dsm = reinterpret_cast<float*>(sA);
    #pragma unroll
    for(int mt = 0; mt < 2; mt++){
        int px = wM*32 + mt*16 + (lane >> 2);
        #pragma unroll
        for(int nt = 0; nt < 8; nt++){
            int oc = wN*64 + nt*8 + (lane & 3)*2;
            #pragma unroll
            for(int e = 0; e < 4; e++){
                int p = px + (e >> 1)*8;
                int o = oc + (e & 1);
                Dsm[p*129 + o] = d[mt][nt][e] + s_bias[o];
            }
        }
    }
    // --- load G tables into smem (reuse W region) ---
    float* tGg = reinterpret_cast<float*>(sW);
    float* tGb = tGg + 7*584;
    for(int i = tid; i < 7*584; i += 256){
        int r = i/584, k = i%584;
        float vg = 0.f, vb = 0.f;
        if(r < 6 && k < 576){ vg = g_Gg[(b*6+r)*576 + k]; vb = g_Gb[(b*6+r)*576 + k]; }
        tGg[i] = vg; tGb[i] = vb;
    }
    __syncthreads();

    // --- fused final: 256 threads = 128 px x 2 channel-halves ---
    float ga = 1.f/(1.f + expf(-bg[0]));
    float ba = 1.f/(1.f + expf(-bb2[0]));
    int px = tid & 127;
    int half = tid >> 7;
    int base[9];
    #pragma unroll
    for(int tap = 0; tap < 9; tap++){
        int dy = tap/3 - 1, dx = tap%3 - 1;
        int yy = y + dy, xx = px + dx;
        int r = 6;
        if(yy >= 0 && yy < 128 && xx >= 0 && xx < 128) r = g_region[(b<<14) + (yy<<7) + xx];
        base[tap] = r*584 + tap*64;
    }
    float nz = noise[(b<<14) + (px<<7) + y];   // noiseT[y][px] = noise[px][y]
    size_t pix = (size_t)(y<<7) + px;
    for(int jj = 0; jj < 8; jj++){
        int j = half*8 + jj;
        unsigned long long ag0=0ull, ag1=0ull, ab0=0ull, ab1=0ull;
        #pragma unroll
        for(int tap = 0; tap < 9; tap++){
            const ulonglong2* pgp = reinterpret_cast<const ulonglong2*>(&tGg[base[tap] + j*4]);
            const ulonglong2* pbp = reinterpret_cast<const ulonglong2*>(&tGb[base[tap] + j*4]);
            ulonglong2 vg = *pgp, vb = *pbp;
            add2(ag0, vg.x); add2(ag1, vg.y);
            add2(ab0, vb.x); add2(ab1, vb.y);
        }
        float g4[4], b4[4];
        upk2(ag0, g4[0], g4[1]); upk2(ag1, g4[2], g4[3]);
        upk2(ab0, b4[0], b4[1]); upk2(ab1, b4[2], b4[3]);
        #pragma unroll
        for(int k = 0; k < 4; k++){
            int c = j*4 + k;
            size_t idx = (((size_t)(b*64 + c))<<14) + pix;
            float xv = x[idx] + s_nv[c]*nz;
            float xn = (xv - s_mean[c])*s_rstd[c];
            float gf = ga*(g4[k] + s_gb[c]) + (1.f - ga)*Dsm[px*129 + c];
            float bf = ba*(b4[k] + s_bb[c]) + (1.f - ba)*Dsm[px*129 + 64 + c];
            out[idx] = xn*(1.f + gf) + bf;
        }
    }
}

extern "C" void kernel_launch(void* const* d_in, const int* in_sizes, int n_in,
                              void* d_out, int out_size) {
    const float* x      = (const float*)d_in[0];
    const float* segmap = (const float*)d_in[1];
    const float* mask   = (const float*)d_in[2];
    const float* codes  = (const float*)d_in[3];
    const float* noise  = (const float*)d_in[4];
    const float* nvar   = (const float*)d_in[5];
    const float* fc_w   = (const float*)d_in[6];
    const float* fc_b   = (const float*)d_in[7];
    const float* cg_w   = (const float*)d_in[8];
    const float* cg_b   = (const float*)d_in[9];
    const float* cb_w   = (const float*)d_in[10];
    const float* cb_b   = (const float*)d_in[11];
    const float* ss_w   = (const float*)d_in[12];
    const float* ss_b   = (const float*)d_in[13];
    const float* sg_w   = (const float*)d_in[14];
    const float* sg_b   = (const float*)d_in[15];
    const float* sb_w   = (const float*)d_in[16];
    const float* sb_b   = (const float*)d_in[17];
    const float* bgam   = (const float*)d_in[18];
    const float* bbet   = (const float*)d_in[19];
    float* out = (float*)d_out;

    cudaFuncSetAttribute(spade_fused_kernel,
                         cudaFuncAttributeMaxDynamicSharedMemorySize, SPADE_SMEM);
    cudaFuncSetAttribute(gtab2_kernel,
                         cudaFuncAttributeMaxDynamicSharedMemorySize, GTAB_SMEM);

    stats_kernel<<<256, 256>>>(x, noise, nvar);
    mmu_kernel<<<dim3(24,8), 256>>>(codes, fc_w, fc_b);
    gtab2_kernel<<<128, 256, GTAB_SMEM>>>(cg_w, cb_w);
    prep_kernel<<<832, 256>>>(sg_w, sb_w, segmap);
    actv_kernel<<<dim3(128,4), 128>>>(mask, ss_w, ss_b);
    spade_fused_kernel<<<dim3(128,4), 256, SPADE_SMEM>>>(
        x, noise, nvar, sg_b, sb_b, cg_b, cb_b, bgam, bbet, out);
}

// round 9
// speedup vs baseline: 3.2348x; 1.0642x over previous
#include <cuda_runtime.h>
#include <cuda_bf16.h>
#include <math.h>

#define HW_ 16384

// ---------------- scratch (static device globals; no allocation) ----------------
__device__ __nv_bfloat16 g_actvB[4*HW_*128];   // NHWC bf16: [b][y][x][ic]
__device__ __nv_bfloat16 g_wBp[9*128*128];     // [tap][oc][ic] bf16
__device__ float g_mean[256];
__device__ float g_rstd[256];
__device__ float g_mmu[4*6*512];
__device__ float g_Gg[4*6*576];
__device__ float g_Gb[4*6*576];
__device__ unsigned char g_region[4*HW_];

// ---------------- f32x2 helpers ----------------
__device__ __forceinline__ void upk2(unsigned long long v, float& a, float& b){
    asm("mov.b64 {%0,%1}, %2;" : "=f"(a), "=f"(b) : "l"(v));
}
__device__ __forceinline__ void add2(unsigned long long& d, unsigned long long a){
    asm("add.rn.f32x2 %0, %1, %2;" : "=l"(d) : "l"(a), "l"(d));
}

// ---------------- mma / ldmatrix / cp.async helpers (sm_80+ portable) ----------------
__device__ __forceinline__ unsigned smem_u32(const void* p){
    unsigned r; asm("{ .reg .u64 t; cvta.to.shared.u64 t, %1; cvt.u32.u64 %0, t; }" : "=r"(r) : "l"(p));
    return r;
}
__device__ __forceinline__ void ldmx4(unsigned* r, unsigned addr){
    asm volatile("ldmatrix.sync.aligned.m8n8.x4.shared.b16 {%0,%1,%2,%3}, [%4];"
        : "=r"(r[0]),"=r"(r[1]),"=r"(r[2]),"=r"(r[3]) : "r"(addr));
}
__device__ __forceinline__ void ldmx2(unsigned* r, unsigned addr){
    asm volatile("ldmatrix.sync.aligned.m8n8.x2.shared.b16 {%0,%1}, [%2];"
        : "=r"(r[0]),"=r"(r[1]) : "r"(addr));
}
__device__ __forceinline__ void mma16816(float* d, const unsigned* a, const unsigned* bq){
    asm volatile("mma.sync.aligned.m16n8k16.row.col.f32.bf16.bf16.f32 "
        "{%0,%1,%2,%3}, {%4,%5,%6,%7}, {%8,%9}, {%0,%1,%2,%3};"
        : "+f"(d[0]),"+f"(d[1]),"+f"(d[2]),"+f"(d[3])
        : "r"(a[0]),"r"(a[1]),"r"(a[2]),"r"(a[3]), "r"(bq[0]),"r"(bq[1]));
}
__device__ __forceinline__ void cpa16(unsigned dst, const void* src){
    asm volatile("cp.async.cg.shared.global [%0], [%1], 16;" :: "r"(dst), "l"(src) : "memory");
}
#define CPA_COMMIT() asm volatile("cp.async.commit_group;" ::: "memory")
#define CPA_WAIT0()  asm volatile("cp.async.wait_group 0;" ::: "memory")

// ---------------- K1: fused prep = stats (0..255) | wtrans (256..831) | region (832..1087) ----------------
__global__ void __launch_bounds__(256) fusedprep_kernel(
        const float* __restrict__ x, const float* __restrict__ noise,
        const float* __restrict__ nvar,
        const float* __restrict__ swg, const float* __restrict__ swb,
        const float* __restrict__ segmap){
    int blk = blockIdx.x;
    if(blk < 256){
        // --- instance-norm stats (noise read transposed in-place) ---
        int bc = blk; int b = bc >> 6, c = bc & 63;
        float nv = nvar[c];
        const float4* xp = reinterpret_cast<const float4*>(x + (size_t)bc*HW_);
        const float* nb = noise + (b<<14);
        float s = 0.f, ss = 0.f;
        for(int i = threadIdx.x; i < HW_/4; i += 256){
            float4 xv = xp[i];
            int p4 = i*4;
            int h = p4 >> 7, w0 = p4 & 127;
            float n0 = nb[((w0  )<<7) + h];
            float n1 = nb[((w0+1)<<7) + h];
            float n2 = nb[((w0+2)<<7) + h];
            float n3 = nb[((w0+3)<<7) + h];
            float v;
            v = xv.x + nv*n0; s += v; ss += v*v;
            v = xv.y + nv*n1; s += v; ss += v*v;
            v = xv.z + nv*n2; s += v; ss += v*v;
            v = xv.w + nv*n3; s += v; ss += v*v;
        }
        __shared__ float rs[256], rq[256];
        rs[threadIdx.x] = s; rq[threadIdx.x] = ss;
        __syncthreads();
        for(int st = 128; st > 0; st >>= 1){
            if(threadIdx.x < st){ rs[threadIdx.x] += rs[threadIdx.x+st]; rq[threadIdx.x] += rq[threadIdx.x+st]; }
            __syncthreads();
        }
        if(threadIdx.x == 0){
            float m = rs[0]*(1.f/HW_);
            float var = rq[0]*(1.f/HW_) - m*m;
            g_mean[bc] = m;
            g_rstd[bc] = rsqrtf(var + 1e-5f);
        }
    }else if(blk < 832){
        // --- spade weights -> [tap][oc][ic] bf16 ---
        int i = (blk-256)*256 + threadIdx.x;         // 147456
        int tap = i >> 14; int oc = (i >> 7) & 127; int ic = i & 127;
        float v = (oc < 64) ? swg[(size_t)oc*1152 + ic*9 + tap]
                            : swb[(size_t)(oc-64)*1152 + ic*9 + tap];
        g_wBp[i] = __float2bfloat16(v);
    }else{
        // --- region map ---
        int i = (blk-832)*256 + threadIdx.x;         // 65536
        int b = i >> 14, p = i & 16383;
        unsigned char r = 6;
        #pragma unroll
        for(int j = 0; j < 6; j++)
            if(segmap[((size_t)(b*6+j)<<14) + p] != 0.f) r = (unsigned char)j;
        g_region[i] = r;
    }
}

// ---------------- K2: middle_mu (grid 24 x 8) ----------------
__global__ void __launch_bounds__(256) mmu_kernel(const float* __restrict__ codes,
                                                  const float* __restrict__ fcw,
                                                  const float* __restrict__ fcb){
    int bf = blockIdx.x; int f = bf % 6;
    int og = blockIdx.y;
    int lane = threadIdx.x & 31, warp = threadIdx.x >> 5;
    float c[16];
    const float4* cp = reinterpret_cast<const float4*>(codes + (size_t)bf*512);
    #pragma unroll
    for(int it=0; it<4; it++){
        float4 v = cp[it*32 + lane];
        c[it*4+0]=v.x; c[it*4+1]=v.y; c[it*4+2]=v.z; c[it*4+3]=v.w;
    }
    #pragma unroll
    for(int r = 0; r < 8; r++){
        int o = og*64 + warp*8 + r;
        const float4* wp = reinterpret_cast<const float4*>(fcw + ((size_t)f*512 + o)*512);
        float s = 0.f;
        #pragma unroll
        for(int it=0; it<4; it++){
            float4 w = wp[it*32 + lane];
            s += w.x*c[it*4] + w.y*c[it*4+1] + w.z*c[it*4+2] + w.w*c[it*4+3];
        }
        #pragma unroll
        for(int st=16; st>0; st>>=1) s += __shfl_xor_sync(0xffffffffu, s, st);
        if(lane==0) g_mmu[bf*512+o] = fmaxf(s + fcb[f*512+o], 0.f);
    }
}

// ---------------- K3: gtab (blocks 0..127) | actv (blocks 128..383) ----------------
#define GTAB_SMEM ((4608 + 12288)*4)
__global__ void __launch_bounds__(256) gtab_actv_kernel(
        const float* __restrict__ wg, const float* __restrict__ wb,
        const float* __restrict__ mask,
        const float* __restrict__ ssw, const float* __restrict__ ssb){
    extern __shared__ float gsm[];
    int blk = blockIdx.x;
    int tid = threadIdx.x;
    if(blk < 128){
        // --- G tables, warp-parallel ---
        float* sw = gsm;             // [d*9 + tap]
        float* sm = gsm + 4608;      // [bf*512 + d]
        int table = blk >> 6, oc = blk & 63;
        int lane = tid & 31, warp = tid >> 5;
        const float* w = (table ? wb : wg) + (size_t)oc*4608;
        for(int i = tid; i < 4608; i += 256) sw[i] = w[i];
        for(int i = tid; i < 12288; i += 256) sm[i] = g_mmu[i];
        __syncthreads();
        for(int j = warp*27; j < warp*27 + 27; j++){
            int bf = j / 9, tap = j % 9;
            const float* mrow = &sm[bf*512];
            float acc = 0.f;
            #pragma unroll
            for(int k = 0; k < 16; k++){
                int d = lane + k*32;
                acc += sw[d*9 + tap] * mrow[d];
            }
            #pragma unroll
            for(int st=16; st>0; st>>=1) acc += __shfl_xor_sync(0xffffffffu, acc, st);
            if(lane == 0){
                if(table) g_Gb[bf*576 + tap*64 + oc] = acc;
                else      g_Gg[bf*576 + tap*64 + oc] = acc;
            }
        }
    }else{
        // --- actv = relu(conv3x3(mask 3->128)) -> NHWC bf16; 2 rows per block ---
        float* swt = gsm;            // 3456
        float* sbias = gsm + 3456;   // 128
        int ab = blk - 128;          // 0..255
        int b = ab >> 6;
        int y = (ab & 63)*2 + (tid >> 7);
        int x = tid & 127;
        for(int i = tid; i < 3456; i += 256) swt[i] = ssw[i];
        if(tid < 128) sbias[tid] = ssb[tid];
        float mv[27];
        #pragma unroll
        for(int m = 0; m < 3; m++)
            #pragma unroll
            for(int ky = 0; ky < 3; ky++)
                #pragma unroll
                for(int kx = 0; kx < 3; kx++){
                    int gy = y + ky - 1, gx = x + kx - 1;
                    mv[m*9 + ky*3 + kx] = (gy >= 0 && gy < 128 && gx >= 0 && gx < 128)
                        ? mask[((size_t)(b*3+m)<<14) + (gy<<7) + gx] : 0.f;
                }
        __syncthreads();
        unsigned outp[64];
        for(int icp = 0; icp < 64; icp++){
            float a0 = sbias[2*icp], a1 = sbias[2*icp+1];
            const float* w0 = &swt[(2*icp)*27];
            const float* w1 = w0 + 27;
            #pragma unroll
            for(int k = 0; k < 27; k++){ a0 += mv[k]*w0[k]; a1 += mv[k]*w1[k]; }
            __nv_bfloat162 h = __floats2bfloat162_rn(fmaxf(a0, 0.f), fmaxf(a1, 0.f));
            outp[icp] = *reinterpret_cast<unsigned*>(&h);
        }
        uint4* dst = reinterpret_cast<uint4*>(g_actvB) + ((size_t)((b<<14) + (y<<7) + x))*16;
        const uint4* srcp = reinterpret_cast<const uint4*>(outp);
        #pragma unroll
        for(int i = 0; i < 16; i++) dst[i] = srcp[i];
    }
}

// ---------------- K4: SPADE conv (mma.sync bf16) + FUSED final epilogue ----------------
#define APLANE 17680             // 130*136 elems
#define WBUF   17408             // 128*136 elems
#define SPADE_SMEM ((3*APLANE + 2*WBUF)*2)

__global__ void __launch_bounds__(256) spade_fused_kernel(
        const float* __restrict__ x,   const float* __restrict__ noise,
        const float* __restrict__ nvar,
        const float* __restrict__ sgb, const float* __restrict__ sbb,
        const float* __restrict__ cgb, const float* __restrict__ cbb,
        const float* __restrict__ bg,  const float* __restrict__ bb2,
        float* __restrict__ out){
    extern __shared__ __align__(16) unsigned char dynsm[];
    __nv_bfloat16* sA = reinterpret_cast<__nv_bfloat16*>(dynsm);
    __nv_bfloat16* sW = sA + 3*APLANE;
    __shared__ float s_bias[128];
    __shared__ float s_mean[64], s_rstd[64], s_nv[64], s_gb[64], s_bb[64];

    int y = blockIdx.x, b = blockIdx.y;
    int tid = threadIdx.x;
    if(tid < 128) s_bias[tid] = (tid < 64) ? sgb[tid] : sbb[tid-64];
    else{
        int t = tid - 128;
        if(t < 64){
            s_mean[t] = g_mean[b*64+t]; s_rstd[t] = g_rstd[b*64+t];
            s_nv[t] = nvar[t]; s_gb[t] = cgb[t]; s_bb[t] = cbb[t];
        }
    }

    // --- stage A halo rows + zero borders/OOB planes ---
    for(int dy = 0; dy < 3; dy++){
        int sr = y + dy - 1;
        uint4* plane4 = reinterpret_cast<uint4*>(sA + dy*APLANE);
        if(sr < 0 || sr > 127){
            for(int i = tid; i < 2210; i += 256) plane4[i] = make_uint4(0,0,0,0);
        }else{
            if(tid < 17) plane4[tid] = make_uint4(0,0,0,0);                    // px -1
            else if(tid < 34) plane4[129*17 + (tid-17)] = make_uint4(0,0,0,0); // px 128
            const __nv_bfloat16* src = g_actvB + ((size_t)((b<<14) + (sr<<7)))*128;
            for(int i = tid; i < 2048; i += 256){
                int px = i >> 4, ch = i & 15;
                cpa16(smem_u32(sA + dy*APLANE + (px+1)*136 + ch*8), src + px*128 + ch*8);
            }
        }
    }
    // --- prefetch W tap 0 ---
    for(int i = tid; i < 2048; i += 256){
        int n = i >> 4, ch = i & 15;
        cpa16(smem_u32(sW + n*136 + ch*8), g_wBp + n*128 + ch*8);
    }
    CPA_COMMIT();
    CPA_WAIT0();
    __syncthreads();

    int lane = tid & 31, warp = tid >> 5;
    int wM = warp & 3, wN = warp >> 2;
    unsigned sA_u = smem_u32(sA);
    unsigned sW_u = smem_u32(sW);

    float d[2][8][4];
    #pragma unroll
    for(int mt=0; mt<2; mt++)
        #pragma unroll
        for(int nt=0; nt<8; nt++)
            #pragma unroll
            for(int e=0; e<4; e++) d[mt][nt][e] = 0.f;

    int aRow = (lane & 15);
    int aHalf = (lane >> 4);
    int bN = lane & 7;
    int bHalf = (lane >> 3) & 1;

    for(int tap = 0; tap < 9; tap++){
        if(tap < 8){
            const __nv_bfloat16* src = g_wBp + (tap+1)*16384;
            __nv_bfloat16* dstb = sW + ((tap+1) & 1)*WBUF;
            for(int i = tid; i < 2048; i += 256){
                int n = i >> 4, ch = i & 15;
                cpa16(smem_u32(dstb + n*136 + ch*8), src + n*128 + ch*8);
            }
            CPA_COMMIT();
        }
        int dy = tap/3, dx = tap%3;
        unsigned aBase = sA_u + (unsigned)(dy*APLANE)*2;
        unsigned wBase = sW_u + (unsigned)((tap & 1)*WBUF)*2;
        #pragma unroll
        for(int ks = 0; ks < 8; ks++){
            unsigned a[2][4];
            #pragma unroll
            for(int mt = 0; mt < 2; mt++){
                unsigned ad = aBase + (unsigned)(((wM*32 + mt*16 + aRow + dx)*136
                                 + ks*16 + aHalf*8) << 1);
                ldmx4(a[mt], ad);
            }
            unsigned bq[8][2];
            #pragma unroll
            for(int nt = 0; nt < 8; nt++){
                unsigned bd = wBase + (unsigned)(((wN*64 + nt*8 + bN)*136
                                 + ks*16 + bHalf*8) << 1);
                ldmx2(bq[nt], bd);
            }
            #pragma unroll
            for(int mt = 0; mt < 2; mt++)
                #pragma unroll
                for(int nt = 0; nt < 8; nt++)
                    mma16816(d[mt][nt], a[mt], bq[nt]);
        }
        CPA_WAIT0();
        __syncthreads();
    }

    // --- dump D (+spade bias) into smem (reuse A region), pitch 129 ---
    float* Dsm = reinterpret_cast<float*>(sA);
    #pragma unroll
    for(int mt = 0; mt < 2; mt++){
        int px = wM*32 + mt*16 + (lane >> 2);
        #pragma unroll
        for(int nt = 0; nt < 8; nt++){
            int oc = wN*64 + nt*8 + (lane & 3)*2;
            #pragma unroll
            for(int e = 0; e < 4; e++){
                int p = px + (e >> 1)*8;
                int o = oc + (e & 1);
                Dsm[p*129 + o] = d[mt][nt][e] + s_bias[o];
            }
        }
    }
    // --- load G tables into smem (reuse W region) ---
    float* tGg = reinterpret_cast<float*>(sW);
    float* tGb = tGg + 7*584;
    for(int i = tid; i < 7*584; i += 256){
        int r = i/584, k = i%584;
        float vg = 0.f, vb = 0.f;
        if(r < 6 && k < 576){ vg = g_Gg[(b*6+r)*576 + k]; vb = g_Gb[(b*6+r)*576 + k]; }
        tGg[i] = vg; tGb[i] = vb;
    }
    __syncthreads();

    // --- fused final: 256 threads = 128 px x 2 channel-halves ---
    float ga = 1.f/(1.f + expf(-bg[0]));
    float ba = 1.f/(1.f + expf(-bb2[0]));
    int px = tid & 127;
    int half = tid >> 7;
    int base[9];
    #pragma unroll
    for(int tap = 0; tap < 9; tap++){
        int dy = tap/3 - 1, dx = tap%3 - 1;
        int yy = y + dy, xx = px + dx;
        int r = 6;
        if(yy >= 0 && yy < 128 && xx >= 0 && xx < 128) r = g_region[(b<<14) + (yy<<7) + xx];
        base[tap] = r*584 + tap*64;
    }
    float nz = noise[(b<<14) + (px<<7) + y];   // noiseT[y][px] = noise[px][y]
    size_t pix = (size_t)(y<<7) + px;
    for(int jj = 0; jj < 8; jj++){
        int j = half*8 + jj;
        unsigned long long ag0=0ull, ag1=0ull, ab0=0ull, ab1=0ull;
        #pragma unroll
        for(int tap = 0; tap < 9; tap++){
            const ulonglong2* pgp = reinterpret_cast<const ulonglong2*>(&tGg[base[tap] + j*4]);
            const ulonglong2* pbp = reinterpret_cast<const ulonglong2*>(&tGb[base[tap] + j*4]);
            ulonglong2 vg = *pgp, vb = *pbp;
            add2(ag0, vg.x); add2(ag1, vg.y);
            add2(ab0, vb.x); add2(ab1, vb.y);
        }
        float g4[4], b4[4];
        upk2(ag0, g4[0], g4[1]); upk2(ag1, g4[2], g4[3]);
        upk2(ab0, b4[0], b4[1]); upk2(ab1, b4[2], b4[3]);
        #pragma unroll
        for(int k = 0; k < 4; k++){
            int c = j*4 + k;
            size_t idx = (((size_t)(b*64 + c))<<14) + pix;
            float xv = x[idx] + s_nv[c]*nz;
            float xn = (xv - s_mean[c])*s_rstd[c];
            float gf = ga*(g4[k] + s_gb[c]) + (1.f - ga)*Dsm[px*129 + c];
            float bf = ba*(b4[k] + s_bb[c]) + (1.f - ba)*Dsm[px*129 + 64 + c];
            out[idx] = xn*(1.f + gf) + bf;
        }
    }
}

extern "C" void kernel_launch(void* const* d_in, const int* in_sizes, int n_in,
                              void* d_out, int out_size) {
    const float* x      = (const float*)d_in[0];
    const float* segmap = (const float*)d_in[1];
    const float* mask   = (const float*)d_in[2];
    const float* codes  = (const float*)d_in[3];
    const float* noise  = (const float*)d_in[4];
    const float* nvar   = (const float*)d_in[5];
    const float* fc_w   = (const float*)d_in[6];
    const float* fc_b   = (const float*)d_in[7];
    const float* cg_w   = (const float*)d_in[8];
    const float* cg_b   = (const float*)d_in[9];
    const float* cb_w   = (const float*)d_in[10];
    const float* cb_b   = (const float*)d_in[11];
    const float* ss_w   = (const float*)d_in[12];
    const float* ss_b   = (const float*)d_in[13];
    const float* sg_w   = (const float*)d_in[14];
    const float* sg_b   = (const float*)d_in[15];
    const float* sb_w   = (const float*)d_in[16];
    const float* sb_b   = (const float*)d_in[17];
    const float* bgam   = (const float*)d_in[18];
    const float* bbet   = (const float*)d_in[19];
    float* out = (float*)d_out;

    cudaFuncSetAttribute(spade_fused_kernel,
                         cudaFuncAttributeMaxDynamicSharedMemorySize, SPADE_SMEM);
    cudaFuncSetAttribute(gtab_actv_kernel,
                         cudaFuncAttributeMaxDynamicSharedMemorySize, GTAB_SMEM);

    fusedprep_kernel<<<1088, 256>>>(x, noise, nvar, sg_w, sb_w, segmap);
    mmu_kernel<<<dim3(24,8), 256>>>(codes, fc_w, fc_b);
    gtab_actv_kernel<<<384, 256, GTAB_SMEM>>>(cg_w, cb_w, mask, ss_w, ss_b);
    spade_fused_kernel<<<dim3(128,4), 256, SPADE_SMEM>>>(
        x, noise, nvar, sg_b, sb_b, cg_b, cb_b, bgam, bbet, out);
}

// round 10
// speedup vs baseline: 3.7332x; 1.1541x over previous
#include <cuda_runtime.h>
#include <cuda_bf16.h>
#include <math.h>

#define HW_ 16384

// ---------------- scratch (static device globals; no allocation) ----------------
__device__ __nv_bfloat16 g_actvB[4*HW_*128];   // NHWC bf16: [b][y][x][ic]
__device__ __nv_bfloat16 g_wBp[9*128*128];     // [tap][oc][ic] bf16
__device__ float g_mean[256];
__device__ float g_rstd[256];
__device__ float g_mmu[4*6*512];
__device__ float g_Gg[4*6*576];
__device__ float g_Gb[4*6*576];
__device__ unsigned char g_region[4*HW_];

// ---------------- f32x2 helpers ----------------
__device__ __forceinline__ void upk2(unsigned long long v, float& a, float& b){
    asm("mov.b64 {%0,%1}, %2;" : "=f"(a), "=f"(b) : "l"(v));
}
__device__ __forceinline__ void add2(unsigned long long& d, unsigned long long a){
    asm("add.rn.f32x2 %0, %1, %2;" : "=l"(d) : "l"(a), "l"(d));
}

// ---------------- mma / ldmatrix / cp.async helpers (sm_80+ portable) ----------------
__device__ __forceinline__ unsigned smem_u32(const void* p){
    unsigned r; asm("{ .reg .u64 t; cvta.to.shared.u64 t, %1; cvt.u32.u64 %0, t; }" : "=r"(r) : "l"(p));
    return r;
}
__device__ __forceinline__ void ldmx4(unsigned* r, unsigned addr){
    asm volatile("ldmatrix.sync.aligned.m8n8.x4.shared.b16 {%0,%1,%2,%3}, [%4];"
        : "=r"(r[0]),"=r"(r[1]),"=r"(r[2]),"=r"(r[3]) : "r"(addr));
}
__device__ __forceinline__ void ldmx2(unsigned* r, unsigned addr){
    asm volatile("ldmatrix.sync.aligned.m8n8.x2.shared.b16 {%0,%1}, [%2];"
        : "=r"(r[0]),"=r"(r[1]) : "r"(addr));
}
__device__ __forceinline__ void mma16816(float* d, const unsigned* a, const unsigned* bq){
    asm volatile("mma.sync.aligned.m16n8k16.row.col.f32.bf16.bf16.f32 "
        "{%0,%1,%2,%3}, {%4,%5,%6,%7}, {%8,%9}, {%0,%1,%2,%3};"
        : "+f"(d[0]),"+f"(d[1]),"+f"(d[2]),"+f"(d[3])
        : "r"(a[0]),"r"(a[1]),"r"(a[2]),"r"(a[3]), "r"(bq[0]),"r"(bq[1]));
}
__device__ __forceinline__ void cpa16(unsigned dst, const void* src){
    asm volatile("cp.async.cg.shared.global [%0], [%1], 16;" :: "r"(dst), "l"(src) : "memory");
}
#define CPA_COMMIT() asm volatile("cp.async.commit_group;" ::: "memory")
#define CPA_WAIT0()  asm volatile("cp.async.wait_group 0;" ::: "memory")

// ---------------- K1: fused prep = stats (0..255) | wtrans (256..831) | region (832..1087) ----------------
__global__ void __launch_bounds__(256) fusedprep_kernel(
        const float* __restrict__ x, const float* __restrict__ noise,
        const float* __restrict__ nvar,
        const float* __restrict__ swg, const float* __restrict__ swb,
        const float* __restrict__ segmap){
    int blk = blockIdx.x;
    if(blk < 256){
        int bc = blk; int b = bc >> 6, c = bc & 63;
        float nv = nvar[c];
        const float4* xp = reinterpret_cast<const float4*>(x + (size_t)bc*HW_);
        const float* nb = noise + (b<<14);
        float s = 0.f, ss = 0.f;
        for(int i = threadIdx.x; i < HW_/4; i += 256){
            float4 xv = xp[i];
            int p4 = i*4;
            int h = p4 >> 7, w0 = p4 & 127;
            float n0 = nb[((w0  )<<7) + h];
            float n1 = nb[((w0+1)<<7) + h];
            float n2 = nb[((w0+2)<<7) + h];
            float n3 = nb[((w0+3)<<7) + h];
            float v;
            v = xv.x + nv*n0; s += v; ss += v*v;
            v = xv.y + nv*n1; s += v; ss += v*v;
            v = xv.z + nv*n2; s += v; ss += v*v;
            v = xv.w + nv*n3; s += v; ss += v*v;
        }
        __shared__ float rs[256], rq[256];
        rs[threadIdx.x] = s; rq[threadIdx.x] = ss;
        __syncthreads();
        for(int st = 128; st > 0; st >>= 1){
            if(threadIdx.x < st){ rs[threadIdx.x] += rs[threadIdx.x+st]; rq[threadIdx.x] += rq[threadIdx.x+st]; }
            __syncthreads();
        }
        if(threadIdx.x == 0){
            float m = rs[0]*(1.f/HW_);
            float var = rq[0]*(1.f/HW_) - m*m;
            g_mean[bc] = m;
            g_rstd[bc] = rsqrtf(var + 1e-5f);
        }
    }else if(blk < 832){
        int i = (blk-256)*256 + threadIdx.x;         // 147456
        int tap = i >> 14; int oc = (i >> 7) & 127; int ic = i & 127;
        float v = (oc < 64) ? swg[(size_t)oc*1152 + ic*9 + tap]
                            : swb[(size_t)(oc-64)*1152 + ic*9 + tap];
        g_wBp[i] = __float2bfloat16(v);
    }else{
        int i = (blk-832)*256 + threadIdx.x;         // 65536
        int b = i >> 14, p = i & 16383;
        unsigned char r = 6;
        #pragma unroll
        for(int j = 0; j < 6; j++)
            if(segmap[((size_t)(b*6+j)<<14) + p] != 0.f) r = (unsigned char)j;
        g_region[i] = r;
    }
}

// ---------------- K2: middle_mu (grid 24 x 8) ----------------
__global__ void __launch_bounds__(256) mmu_kernel(const float* __restrict__ codes,
                                                  const float* __restrict__ fcw,
                                                  const float* __restrict__ fcb){
    int bf = blockIdx.x; int f = bf % 6;
    int og = blockIdx.y;
    int lane = threadIdx.x & 31, warp = threadIdx.x >> 5;
    float c[16];
    const float4* cp = reinterpret_cast<const float4*>(codes + (size_t)bf*512);
    #pragma unroll
    for(int it=0; it<4; it++){
        float4 v = cp[it*32 + lane];
        c[it*4+0]=v.x; c[it*4+1]=v.y; c[it*4+2]=v.z; c[it*4+3]=v.w;
    }
    #pragma unroll
    for(int r = 0; r < 8; r++){
        int o = og*64 + warp*8 + r;
        const float4* wp = reinterpret_cast<const float4*>(fcw + ((size_t)f*512 + o)*512);
        float s = 0.f;
        #pragma unroll
        for(int it=0; it<4; it++){
            float4 w = wp[it*32 + lane];
            s += w.x*c[it*4] + w.y*c[it*4+1] + w.z*c[it*4+2] + w.w*c[it*4+3];
        }
        #pragma unroll
        for(int st=16; st>0; st>>=1) s += __shfl_xor_sync(0xffffffffu, s, st);
        if(lane==0) g_mmu[bf*512+o] = fmaxf(s + fcb[f*512+o], 0.f);
    }
}

// ---------------- K3: gtab (blocks 0..127) | actv (blocks 128..383) ----------------
#define GTAB_SMEM ((4608 + 12288)*4)
__global__ void __launch_bounds__(256) gtab_actv_kernel(
        const float* __restrict__ wg, const float* __restrict__ wb,
        const float* __restrict__ mask,
        const float* __restrict__ ssw, const float* __restrict__ ssb){
    extern __shared__ float gsm[];
    int blk = blockIdx.x;
    int tid = threadIdx.x;
    if(blk < 128){
        float* sw = gsm;
        float* sm = gsm + 4608;
        int table = blk >> 6, oc = blk & 63;
        int lane = tid & 31, warp = tid >> 5;
        const float* w = (table ? wb : wg) + (size_t)oc*4608;
        for(int i = tid; i < 4608; i += 256) sw[i] = w[i];
        for(int i = tid; i < 12288; i += 256) sm[i] = g_mmu[i];
        __syncthreads();
        for(int j = warp*27; j < warp*27 + 27; j++){
            int bf = j / 9, tap = j % 9;
            const float* mrow = &sm[bf*512];
            float acc = 0.f;
            #pragma unroll
            for(int k = 0; k < 16; k++){
                int d = lane + k*32;
                acc += sw[d*9 + tap] * mrow[d];
            }
            #pragma unroll
            for(int st=16; st>0; st>>=1) acc += __shfl_xor_sync(0xffffffffu, acc, st);
            if(lane == 0){
                if(table) g_Gb[bf*576 + tap*64 + oc] = acc;
                else      g_Gg[bf*576 + tap*64 + oc] = acc;
            }
        }
    }else{
        float* swt = gsm;
        float* sbias = gsm + 3456;
        int ab = blk - 128;
        int b = ab >> 6;
        int y = (ab & 63)*2 + (tid >> 7);
        int x = tid & 127;
        for(int i = tid; i < 3456; i += 256) swt[i] = ssw[i];
        if(tid < 128) sbias[tid] = ssb[tid];
        float mv[27];
        #pragma unroll
        for(int m = 0; m < 3; m++)
            #pragma unroll
            for(int ky = 0; ky < 3; ky++)
                #pragma unroll
                for(int kx = 0; kx < 3; kx++){
                    int gy = y + ky - 1, gx = x + kx - 1;
                    mv[m*9 + ky*3 + kx] = (gy >= 0 && gy < 128 && gx >= 0 && gx < 128)
                        ? mask[((size_t)(b*3+m)<<14) + (gy<<7) + gx] : 0.f;
                }
        __syncthreads();
        unsigned outp[64];
        for(int icp = 0; icp < 64; icp++){
            float a0 = sbias[2*icp], a1 = sbias[2*icp+1];
            const float* w0 = &swt[(2*icp)*27];
            const float* w1 = w0 + 27;
            #pragma unroll
            for(int k = 0; k < 27; k++){ a0 += mv[k]*w0[k]; a1 += mv[k]*w1[k]; }
            __nv_bfloat162 h = __floats2bfloat162_rn(fmaxf(a0, 0.f), fmaxf(a1, 0.f));
            outp[icp] = *reinterpret_cast<unsigned*>(&h);
        }
        uint4* dst = reinterpret_cast<uint4*>(g_actvB) + ((size_t)((b<<14) + (y<<7) + x))*16;
        const uint4* srcp = reinterpret_cast<const uint4*>(outp);
        #pragma unroll
        for(int i = 0; i < 16; i++) dst[i] = srcp[i];
    }
}

// ---------------- K4: SPADE conv (mma.sync bf16, 2 rows/block, 512 thr) + FUSED final ----------------
#define APLANE 17680             // 130*136 elems
#define WBUF   17408             // 128*136 elems
#define SPADE_SMEM ((4*APLANE + 2*WBUF)*2)

__global__ void __launch_bounds__(512) spade_fused_kernel(
        const float* __restrict__ x,   const float* __restrict__ noise,
        const float* __restrict__ nvar,
        const float* __restrict__ sgb, const float* __restrict__ sbb,
        const float* __restrict__ cgb, const float* __restrict__ cbb,
        const float* __restrict__ bg,  const float* __restrict__ bb2,
        float* __restrict__ out){
    extern __shared__ __align__(16) unsigned char dynsm[];
    __nv_bfloat16* sA = reinterpret_cast<__nv_bfloat16*>(dynsm);   // 4 halo planes
    __nv_bfloat16* sW = sA + 4*APLANE;
    __shared__ float s_bias[128];
    __shared__ float s_mean[64], s_rstd[64], s_nv[64], s_gb[64], s_bb[64];

    int y0 = blockIdx.x*2, b = blockIdx.y;
    int tid = threadIdx.x;
    if(tid < 128) s_bias[tid] = (tid < 64) ? sgb[tid] : sbb[tid-64];
    else if(tid < 192){
        int t = tid - 128;
        s_mean[t] = g_mean[b*64+t]; s_rstd[t] = g_rstd[b*64+t];
        s_nv[t] = nvar[t]; s_gb[t] = cgb[t]; s_bb[t] = cbb[t];
    }

    // --- stage 4 A halo planes (rows y0-1 .. y0+2) + zero borders/OOB ---
    for(int pl = 0; pl < 4; pl++){
        int sr = y0 + pl - 1;
        uint4* plane4 = reinterpret_cast<uint4*>(sA + pl*APLANE);
        if(sr < 0 || sr > 127){
            for(int i = tid; i < 2210; i += 512) plane4[i] = make_uint4(0,0,0,0);
        }else{
            if(tid < 17) plane4[tid] = make_uint4(0,0,0,0);                    // halo px -1
            else if(tid < 34) plane4[129*17 + (tid-17)] = make_uint4(0,0,0,0); // halo px 128
            const __nv_bfloat16* src = g_actvB + ((size_t)((b<<14) + (sr<<7)))*128;
            for(int i = tid; i < 2048; i += 512){
                int px = i >> 4, ch = i & 15;
                cpa16(smem_u32(sA + pl*APLANE + (px+1)*136 + ch*8), src + px*128 + ch*8);
            }
        }
    }
    // --- prefetch W tap 0 ---
    for(int i = tid; i < 2048; i += 512){
        int n = i >> 4, ch = i & 15;
        cpa16(smem_u32(sW + n*136 + ch*8), g_wBp + n*128 + ch*8);
    }
    CPA_COMMIT();
    CPA_WAIT0();
    __syncthreads();

    int lane = tid & 31, warp = tid >> 5;
    int wM = warp & 3, wN = warp >> 2;     // 4 x 4 warp grid: 64px x 32oc per warp
    int rIdx = wM >> 1;                    // which output row this warp serves
    int pxBase = (wM & 1)*64;              // px base within row
    unsigned sA_u = smem_u32(sA);
    unsigned sW_u = smem_u32(sW);

    float d[4][4][4];
    #pragma unroll
    for(int mt=0; mt<4; mt++)
        #pragma unroll
        for(int nt=0; nt<4; nt++)
            #pragma unroll
            for(int e=0; e<4; e++) d[mt][nt][e] = 0.f;

    int aRow = (lane & 15);
    int aHalf = (lane >> 4);
    int bN = lane & 7;
    int bHalf = (lane >> 3) & 1;

    for(int tap = 0; tap < 9; tap++){
        if(tap < 8){
            const __nv_bfloat16* src = g_wBp + (tap+1)*16384;
            __nv_bfloat16* dstb = sW + ((tap+1) & 1)*WBUF;
            for(int i = tid; i < 2048; i += 512){
                int n = i >> 4, ch = i & 15;
                cpa16(smem_u32(dstb + n*136 + ch*8), src + n*128 + ch*8);
            }
            CPA_COMMIT();
        }
        int dy = tap/3, dx = tap%3;
        unsigned aBase = sA_u + (unsigned)((rIdx + dy)*APLANE)*2;
        unsigned wBase = sW_u + (unsigned)((tap & 1)*WBUF)*2;
        #pragma unroll
        for(int ks = 0; ks < 8; ks++){
            unsigned a[4][4];
            #pragma unroll
            for(int mt = 0; mt < 4; mt++){
                unsigned ad = aBase + (unsigned)(((pxBase + mt*16 + aRow + dx)*136
                                 + ks*16 + aHalf*8) << 1);
                ldmx4(a[mt], ad);
            }
            unsigned bq[4][2];
            #pragma unroll
            for(int nt = 0; nt < 4; nt++){
                unsigned bd = wBase + (unsigned)(((wN*32 + nt*8 + bN)*136
                                 + ks*16 + bHalf*8) << 1);
                ldmx2(bq[nt], bd);
            }
            #pragma unroll
            for(int mt = 0; mt < 4; mt++)
                #pragma unroll
                for(int nt = 0; nt < 4; nt++)
                    mma16816(d[mt][nt], a[mt], bq[nt]);
        }
        CPA_WAIT0();
        __syncthreads();
    }

    // --- dump D (+spade bias) into smem (reuse A region): Dsm[256][129] fp32 ---
    float* Dsm = reinterpret_cast<float*>(sA);
    #pragma unroll
    for(int mt = 0; mt < 4; mt++){
        int m = wM*64 + mt*16 + (lane >> 2);       // 0..255 (= r*128 + px)
        #pragma unroll
        for(int nt = 0; nt < 4; nt++){
            int oc = wN*32 + nt*8 + (lane & 3)*2;
            #pragma unroll
            for(int e = 0; e < 4; e++){
                int mm = m + (e >> 1)*8;
                int o = oc + (e & 1);
                Dsm[mm*129 + o] = d[mt][nt][e] + s_bias[o];
            }
        }
    }
    // --- load G tables into smem (reuse W region) ---
    float* tGg = reinterpret_cast<float*>(sW);
    float* tGb = tGg + 7*584;
    for(int i = tid; i < 7*584; i += 512){
        int r = i/584, k = i%584;
        float vg = 0.f, vb = 0.f;
        if(r < 6 && k < 576){ vg = g_Gg[(b*6+r)*576 + k]; vb = g_Gb[(b*6+r)*576 + k]; }
        tGg[i] = vg; tGb[i] = vb;
    }
    __syncthreads();

    // --- fused final: 512 threads = 2 rows x 128 px x 2 channel-halves ---
    float ga = 1.f/(1.f + expf(-bg[0]));
    float ba = 1.f/(1.f + expf(-bb2[0]));
    int px = tid & 127;
    int half = (tid >> 7) & 1;
    int rr = tid >> 8;
    int y = y0 + rr;
    int base[9];
    #pragma unroll
    for(int tap = 0; tap < 9; tap++){
        int dy = tap/3 - 1, dx = tap%3 - 1;
        int yy = y + dy, xx = px + dx;
        int r = 6;
        if(yy >= 0 && yy < 128 && xx >= 0 && xx < 128) r = g_region[(b<<14) + (yy<<7) + xx];
        base[tap] = r*584 + tap*64;
    }
    float nz = noise[(b<<14) + (px<<7) + y];   // noiseT[y][px] = noise[px][y]
    size_t pix = (size_t)(y<<7) + px;
    int drow = (rr*128 + px)*129;
    for(int jj = 0; jj < 8; jj++){
        int j = half*8 + jj;
        unsigned long long ag0=0ull, ag1=0ull, ab0=0ull, ab1=0ull;
        #pragma unroll
        for(int tap = 0; tap < 9; tap++){
            const ulonglong2* pgp = reinterpret_cast<const ulonglong2*>(&tGg[base[tap] + j*4]);
            const ulonglong2* pbp = reinterpret_cast<const ulonglong2*>(&tGb[base[tap] + j*4]);
            ulonglong2 vg = *pgp, vb = *pbp;
            add2(ag0, vg.x); add2(ag1, vg.y);
            add2(ab0, vb.x); add2(ab1, vb.y);
        }
        float g4[4], b4[4];
        upk2(ag0, g4[0], g4[1]); upk2(ag1, g4[2], g4[3]);
        upk2(ab0, b4[0], b4[1]); upk2(ab1, b4[2], b4[3]);
        #pragma unroll
        for(int k = 0; k < 4; k++){
            int c = j*4 + k;
            size_t idx = (((size_t)(b*64 + c))<<14) + pix;
            float xv = x[idx] + s_nv[c]*nz;
            float xn = (xv - s_mean[c])*s_rstd[c];
            float gf = ga*(g4[k] + s_gb[c]) + (1.f - ga)*Dsm[drow + c];
            float bf = ba*(b4[k] + s_bb[c]) + (1.f - ba)*Dsm[drow + 64 + c];
            out[idx] = xn*(1.f + gf) + bf;
        }
    }
}

extern "C" void kernel_launch(void* const* d_in, const int* in_sizes, int n_in,
                              void* d_out, int out_size) {
    const float* x      = (const float*)d_in[0];
    const float* segmap = (const float*)d_in[1];
    const float* mask   = (const float*)d_in[2];
    const float* codes  = (const float*)d_in[3];
    const float* noise  = (const float*)d_in[4];
    const float* nvar   = (const float*)d_in[5];
    const float* fc_w   = (const float*)d_in[6];
    const float* fc_b   = (const float*)d_in[7];
    const float* cg_w   = (const float*)d_in[8];
    const float* cg_b   = (const float*)d_in[9];
    const float* cb_w   = (const float*)d_in[10];
    const float* cb_b   = (const float*)d_in[11];
    const float* ss_w   = (const float*)d_in[12];
    const float* ss_b   = (const float*)d_in[13];
    const float* sg_w   = (const float*)d_in[14];
    const float* sg_b   = (const float*)d_in[15];
    const float* sb_w   = (const float*)d_in[16];
    const float* sb_b   = (const float*)d_in[17];
    const float* bgam   = (const float*)d_in[18];
    const float* bbet   = (const float*)d_in[19];
    float* out = (float*)d_out;

    cudaFuncSetAttribute(spade_fused_kernel,
                         cudaFuncAttributeMaxDynamicSharedMemorySize, SPADE_SMEM);
    cudaFuncSetAttribute(gtab_actv_kernel,
                         cudaFuncAttributeMaxDynamicSharedMemorySize, GTAB_SMEM);

    fusedprep_kernel<<<1088, 256>>>(x, noise, nvar, sg_w, sb_w, segmap);
    mmu_kernel<<<dim3(24,8), 256>>>(codes, fc_w, fc_b);
    gtab_actv_kernel<<<384, 256, GTAB_SMEM>>>(cg_w, cb_w, mask, ss_w, ss_b);
    spade_fused_kernel<<<dim3(64,4), 512, SPADE_SMEM>>>(
        x, noise, nvar, sg_b, sb_b, cg_b, cb_b, bgam, bbet, out);
}

// round 11
// speedup vs baseline: 4.6808x; 1.2538x over previous
#include <cuda_runtime.h>
#include <cuda_bf16.h>
#include <math.h>

#define HW_ 16384

// ---------------- scratch (static device globals; no allocation) ----------------
__device__ __nv_bfloat16 g_actvB[4*HW_*128];   // NHWC bf16: [b][y][x][ic]
__device__ __nv_bfloat16 g_wBp[9*128*128];     // [tap][oc][ic] bf16
__device__ float g_noiseT[4*HW_];
__device__ float g_mean[256];
__device__ float g_rstd[256];
__device__ float g_mmu[4*6*512];
__device__ float g_Gg[4*6*576];
__device__ float g_Gb[4*6*576];
__device__ unsigned char g_region[4*HW_];

// ---------------- f32x2 helpers ----------------
__device__ __forceinline__ unsigned long long pk2(float a, float b){
    unsigned long long r; asm("mov.b64 %0, {%1,%2};" : "=l"(r) : "f"(a), "f"(b)); return r;
}
__device__ __forceinline__ void upk2(unsigned long long v, float& a, float& b){
    asm("mov.b64 {%0,%1}, %2;" : "=f"(a), "=f"(b) : "l"(v));
}
__device__ __forceinline__ void add2(unsigned long long& d, unsigned long long a){
    asm("add.rn.f32x2 %0, %1, %2;" : "=l"(d) : "l"(a), "l"(d));
}
__device__ __forceinline__ void fma2(unsigned long long& d, unsigned long long a, unsigned long long b){
    asm("fma.rn.f32x2 %0, %1, %2, %3;" : "=l"(d) : "l"(a), "l"(b), "l"(d));
}

// ---------------- mma / ldmatrix / cp.async helpers (sm_80+ portable) ----------------
__device__ __forceinline__ unsigned smem_u32(const void* p){
    unsigned r; asm("{ .reg .u64 t; cvta.to.shared.u64 t, %1; cvt.u32.u64 %0, t; }" : "=r"(r) : "l"(p));
    return r;
}
__device__ __forceinline__ void ldmx4(unsigned* r, unsigned addr){
    asm volatile("ldmatrix.sync.aligned.m8n8.x4.shared.b16 {%0,%1,%2,%3}, [%4];"
        : "=r"(r[0]),"=r"(r[1]),"=r"(r[2]),"=r"(r[3]) : "r"(addr));
}
__device__ __forceinline__ void mma16816(float* d, const unsigned* a, const unsigned* bq){
    asm volatile("mma.sync.aligned.m16n8k16.row.col.f32.bf16.bf16.f32 "
        "{%0,%1,%2,%3}, {%4,%5,%6,%7}, {%8,%9}, {%0,%1,%2,%3};"
        : "+f"(d[0]),"+f"(d[1]),"+f"(d[2]),"+f"(d[3])
        : "r"(a[0]),"r"(a[1]),"r"(a[2]),"r"(a[3]), "r"(bq[0]),"r"(bq[1]));
}
__device__ __forceinline__ void cpa16(unsigned dst, const void* src){
    asm volatile("cp.async.cg.shared.global [%0], [%1], 16;" :: "r"(dst), "l"(src) : "memory");
}
#define CPA_COMMIT() asm volatile("cp.async.commit_group;" ::: "memory")
#define CPA_WAIT0()  asm volatile("cp.async.wait_group 0;" ::: "memory")

// ---------------- K1: prep = wtrans (0..575) | region (576..831) | noiseT (832..1087) ----------------
__global__ void __launch_bounds__(256) fusedprep_kernel(
        const float* __restrict__ swg, const float* __restrict__ swb,
        const float* __restrict__ segmap, const float* __restrict__ noise){
    int blk = blockIdx.x;
    if(blk < 576){
        int i = blk*256 + threadIdx.x;               // 147456
        int tap = i >> 14; int oc = (i >> 7) & 127; int ic = i & 127;
        float v = (oc < 64) ? swg[(size_t)oc*1152 + ic*9 + tap]
                            : swb[(size_t)(oc-64)*1152 + ic*9 + tap];
        g_wBp[i] = __float2bfloat16(v);
    }else if(blk < 832){
        int i = (blk-576)*256 + threadIdx.x;         // 65536
        int b = i >> 14, p = i & 16383;
        unsigned char r = 6;
        #pragma unroll
        for(int j = 0; j < 6; j++)
            if(segmap[((size_t)(b*6+j)<<14) + p] != 0.f) r = (unsigned char)j;
        g_region[i] = r;
    }else{
        int i = (blk-832)*256 + threadIdx.x;         // 65536: noiseT[b][h][w] = noise[b][w][h]
        int b = i >> 14, p = i & 16383;
        int h = p >> 7, w = p & 127;
        g_noiseT[i] = noise[(b<<14) + (w<<7) + h];
    }
}

// ---------------- K2: middle_mu (grid 24 x 8) ----------------
__global__ void __launch_bounds__(256) mmu_kernel(const float* __restrict__ codes,
                                                  const float* __restrict__ fcw,
                                                  const float* __restrict__ fcb){
    int bf = blockIdx.x; int f = bf % 6;
    int og = blockIdx.y;
    int lane = threadIdx.x & 31, warp = threadIdx.x >> 5;
    float c[16];
    const float4* cp = reinterpret_cast<const float4*>(codes + (size_t)bf*512);
    #pragma unroll
    for(int it=0; it<4; it++){
        float4 v = cp[it*32 + lane];
        c[it*4+0]=v.x; c[it*4+1]=v.y; c[it*4+2]=v.z; c[it*4+3]=v.w;
    }
    #pragma unroll
    for(int r = 0; r < 8; r++){
        int o = og*64 + warp*8 + r;
        const float4* wp = reinterpret_cast<const float4*>(fcw + ((size_t)f*512 + o)*512);
        float s = 0.f;
        #pragma unroll
        for(int it=0; it<4; it++){
            float4 w = wp[it*32 + lane];
            s += w.x*c[it*4] + w.y*c[it*4+1] + w.z*c[it*4+2] + w.w*c[it*4+3];
        }
        #pragma unroll
        for(int st=16; st>0; st>>=1) s += __shfl_xor_sync(0xffffffffu, s, st);
        if(lane==0) g_mmu[bf*512+o] = fmaxf(s + fcb[f*512+o], 0.f);
    }
}

// ---------------- K3: gtab (0..127) | actv (128..383) | stats (384..639) ----------------
#define GTAB_SMEM ((4608 + 12288)*4)
__global__ void __launch_bounds__(256) gtab_actv_stats_kernel(
        const float* __restrict__ wg, const float* __restrict__ wb,
        const float* __restrict__ mask,
        const float* __restrict__ ssw, const float* __restrict__ ssb,
        const float* __restrict__ x, const float* __restrict__ nvar){
    extern __shared__ float gsm[];
    int blk = blockIdx.x;
    int tid = threadIdx.x;
    if(blk < 128){
        // --- G tables, warp-parallel ---
        float* sw = gsm;
        float* sm = gsm + 4608;
        int table = blk >> 6, oc = blk & 63;
        int lane = tid & 31, warp = tid >> 5;
        const float* w = (table ? wb : wg) + (size_t)oc*4608;
        for(int i = tid; i < 4608; i += 256) sw[i] = w[i];
        for(int i = tid; i < 12288; i += 256) sm[i] = g_mmu[i];
        __syncthreads();
        for(int j = warp*27; j < warp*27 + 27; j++){
            int bf = j / 9, tap = j % 9;
            const float* mrow = &sm[bf*512];
            float acc = 0.f;
            #pragma unroll
            for(int k = 0; k < 16; k++){
                int d = lane + k*32;
                acc += sw[d*9 + tap] * mrow[d];
            }
            #pragma unroll
            for(int st=16; st>0; st>>=1) acc += __shfl_xor_sync(0xffffffffu, acc, st);
            if(lane == 0){
                if(table) g_Gb[bf*576 + tap*64 + oc] = acc;
                else      g_Gg[bf*576 + tap*64 + oc] = acc;
            }
        }
    }else if(blk < 384){
        // --- actv = relu(conv3x3(mask 3->128)) -> NHWC bf16; f32x2 FMA, packed weights ---
        unsigned long long* sp = reinterpret_cast<unsigned long long*>(gsm);  // [k][icp] packed pairs
        float* sbias = reinterpret_cast<float*>(sp + 1728);
        int ab = blk - 128;
        int b = ab >> 6;
        int y = (ab & 63)*2 + (tid >> 7);
        int xx = tid & 127;
        for(int i = tid; i < 1728; i += 256){
            int k = i >> 6, icp = i & 63;
            sp[i] = pk2(ssw[(2*icp)*27 + k], ssw[(2*icp+1)*27 + k]);
        }
        if(tid < 128) sbias[tid] = ssb[tid];
        unsigned long long am[27];
        #pragma unroll
        for(int m = 0; m < 3; m++)
            #pragma unroll
            for(int ky = 0; ky < 3; ky++)
                #pragma unroll
                for(int kx = 0; kx < 3; kx++){
                    int gy = y + ky - 1, gx = xx + kx - 1;
                    float mv = (gy >= 0 && gy < 128 && gx >= 0 && gx < 128)
                        ? mask[((size_t)(b*3+m)<<14) + (gy<<7) + gx] : 0.f;
                    am[m*9 + ky*3 + kx] = pk2(mv, mv);
                }
        __syncthreads();
        unsigned outp[64];
        for(int icp = 0; icp < 64; icp++){
            unsigned long long acc = pk2(sbias[2*icp], sbias[2*icp+1]);
            #pragma unroll
            for(int k = 0; k < 27; k++) fma2(acc, am[k], sp[k*64 + icp]);
            float a0, a1; upk2(acc, a0, a1);
            __nv_bfloat162 h = __floats2bfloat162_rn(fmaxf(a0, 0.f), fmaxf(a1, 0.f));
            outp[icp] = *reinterpret_cast<unsigned*>(&h);
        }
        uint4* dst = reinterpret_cast<uint4*>(g_actvB) + ((size_t)((b<<14) + (y<<7) + xx))*16;
        const uint4* srcp = reinterpret_cast<const uint4*>(outp);
        #pragma unroll
        for(int i = 0; i < 16; i++) dst[i] = srcp[i];
    }else{
        // --- instance-norm stats (coalesced x + coalesced noiseT) ---
        int bc = blk - 384; int b = bc >> 6;
        float nv = nvar[bc & 63];
        const float4* xp = reinterpret_cast<const float4*>(x + (size_t)bc*HW_);
        const float4* np = reinterpret_cast<const float4*>(g_noiseT + ((size_t)b<<14));
        float s = 0.f, ss = 0.f;
        for(int i = tid; i < HW_/4; i += 256){
            float4 xv = xp[i]; float4 nn = np[i];
            float v;
            v = xv.x + nv*nn.x; s += v; ss += v*v;
            v = xv.y + nv*nn.y; s += v; ss += v*v;
            v = xv.z + nv*nn.z; s += v; ss += v*v;
            v = xv.w + nv*nn.w; s += v; ss += v*v;
        }
        float* rs = gsm; float* rq = gsm + 256;
        rs[tid] = s; rq[tid] = ss;
        __syncthreads();
        for(int st = 128; st > 0; st >>= 1){
            if(tid < st){ rs[tid] += rs[tid+st]; rq[tid] += rq[tid+st]; }
            __syncthreads();
        }
        if(tid == 0){
            float m = rs[0]*(1.f/HW_);
            float var = rq[0]*(1.f/HW_) - m*m;
            g_mean[bc] = m;
            g_rstd[bc] = rsqrtf(var + 1e-5f);
        }
    }
}

// ---------------- K4: SPADE conv (mma.sync bf16, 2 rows/block, 512 thr) + FUSED final ----------------
#define APLANE 17680             // 130*136 elems
#define WBUF   17408             // 128*136 elems
#define SPADE_SMEM ((4*APLANE + 2*WBUF)*2)

__global__ void __launch_bounds__(512) spade_fused_kernel(
        const float* __restrict__ x,   const float* __restrict__ nvar,
        const float* __restrict__ sgb, const float* __restrict__ sbb,
        const float* __restrict__ cgb, const float* __restrict__ cbb,
        const float* __restrict__ bg,  const float* __restrict__ bb2,
        float* __restrict__ out){
    extern __shared__ __align__(16) unsigned char dynsm[];
    __nv_bfloat16* sA = reinterpret_cast<__nv_bfloat16*>(dynsm);   // 4 halo planes
    __nv_bfloat16* sW = sA + 4*APLANE;
    __shared__ float s_bias[128];
    __shared__ float s_mean[64], s_rstd[64], s_nv[64], s_gb[64], s_bb[64];

    int y0 = blockIdx.x*2, b = blockIdx.y;
    int tid = threadIdx.x;
    if(tid < 128) s_bias[tid] = (tid < 64) ? sgb[tid] : sbb[tid-64];
    else if(tid < 192){
        int t = tid - 128;
        s_mean[t] = g_mean[b*64+t]; s_rstd[t] = g_rstd[b*64+t];
        s_nv[t] = nvar[t]; s_gb[t] = cgb[t]; s_bb[t] = cbb[t];
    }

    // --- stage 4 A halo planes (rows y0-1 .. y0+2) + zero borders/OOB ---
    for(int pl = 0; pl < 4; pl++){
        int sr = y0 + pl - 1;
        uint4* plane4 = reinterpret_cast<uint4*>(sA + pl*APLANE);
        if(sr < 0 || sr > 127){
            for(int i = tid; i < 2210; i += 512) plane4[i] = make_uint4(0,0,0,0);
        }else{
            if(tid < 17) plane4[tid] = make_uint4(0,0,0,0);                    // halo px -1
            else if(tid < 34) plane4[129*17 + (tid-17)] = make_uint4(0,0,0,0); // halo px 128
            const __nv_bfloat16* src = g_actvB + ((size_t)((b<<14) + (sr<<7)))*128;
            for(int i = tid; i < 2048; i += 512){
                int px = i >> 4, ch = i & 15;
                cpa16(smem_u32(sA + pl*APLANE + (px+1)*136 + ch*8), src + px*128 + ch*8);
            }
        }
    }
    // --- prefetch W tap 0 ---
    for(int i = tid; i < 2048; i += 512){
        int n = i >> 4, ch = i & 15;
        cpa16(smem_u32(sW + n*136 + ch*8), g_wBp + n*128 + ch*8);
    }
    CPA_COMMIT();
    CPA_WAIT0();
    __syncthreads();

    int lane = tid & 31, warp = tid >> 5;
    int wM = warp & 3, wN = warp >> 2;     // 4 x 4 warp grid: 64px x 32oc per warp
    int rIdx = wM >> 1;
    int pxBase = (wM & 1)*64;
    unsigned sA_u = smem_u32(sA);
    unsigned sW_u = smem_u32(sW);

    float d[4][4][4];
    #pragma unroll
    for(int mt=0; mt<4; mt++)
        #pragma unroll
        for(int nt=0; nt<4; nt++)
            #pragma unroll
            for(int e=0; e<4; e++) d[mt][nt][e] = 0.f;

    int aRow = (lane & 15);
    int aHalf = (lane >> 4);
    int bMi = lane >> 3;                   // 0..3 matrix index for B ldmx4
    int bR = lane & 7;

    for(int tap = 0; tap < 9; tap++){
        if(tap < 8){
            const __nv_bfloat16* src = g_wBp + (tap+1)*16384;
            __nv_bfloat16* dstb = sW + ((tap+1) & 1)*WBUF;
            for(int i = tid; i < 2048; i += 512){
                int n = i >> 4, ch = i & 15;
                cpa16(smem_u32(dstb + n*136 + ch*8), src + n*128 + ch*8);
            }
            CPA_COMMIT();
        }
        int dy = tap/3, dx = tap%3;
        unsigned aBase = sA_u + (unsigned)((rIdx + dy)*APLANE)*2;
        unsigned wBase = sW_u + (unsigned)((tap & 1)*WBUF)*2;
        #pragma unroll
        for(int ks = 0; ks < 8; ks++){
            unsigned a[4][4];
            #pragma unroll
            for(int mt = 0; mt < 4; mt++){
                unsigned ad = aBase + (unsigned)(((pxBase + mt*16 + aRow + dx)*136
                                 + ks*16 + aHalf*8) << 1);
                ldmx4(a[mt], ad);
            }
            unsigned bq[4][2];
            #pragma unroll
            for(int ntp = 0; ntp < 2; ntp++){
                unsigned bd = wBase + (unsigned)(((wN*32 + ntp*16 + (bMi>>1)*8 + bR)*136
                                 + ks*16 + (bMi&1)*8) << 1);
                unsigned t4[4]; ldmx4(t4, bd);
                bq[2*ntp][0]=t4[0]; bq[2*ntp][1]=t4[1];
                bq[2*ntp+1][0]=t4[2]; bq[2*ntp+1][1]=t4[3];
            }
            #pragma unroll
            for(int mt = 0; mt < 4; mt++)
                #pragma unroll
                for(int nt = 0; nt < 4; nt++)
                    mma16816(d[mt][nt], a[mt], bq[nt]);
        }
        CPA_WAIT0();
        __syncthreads();
    }

    // --- dump D (+spade bias) into smem (reuse A region): Dsm[256][129] fp32 ---
    float* Dsm = reinterpret_cast<float*>(sA);
    #pragma unroll
    for(int mt = 0; mt < 4; mt++){
        int m = wM*64 + mt*16 + (lane >> 2);
        #pragma unroll
        for(int nt = 0; nt < 4; nt++){
            int oc = wN*32 + nt*8 + (lane & 3)*2;
            #pragma unroll
            for(int e = 0; e < 4; e++){
                int mm = m + (e >> 1)*8;
                int o = oc + (e & 1);
                Dsm[mm*129 + o] = d[mt][nt][e] + s_bias[o];
            }
        }
    }
    // --- load G tables into smem (reuse W region) ---
    float* tGg = reinterpret_cast<float*>(sW);
    float* tGb = tGg + 7*584;
    for(int i = tid; i < 7*584; i += 512){
        int r = i/584, k = i%584;
        float vg = 0.f, vb = 0.f;
        if(r < 6 && k < 576){ vg = g_Gg[(b*6+r)*576 + k]; vb = g_Gb[(b*6+r)*576 + k]; }
        tGg[i] = vg; tGb[i] = vb;
    }
    __syncthreads();

    // --- fused final: 512 threads = 2 rows x 128 px x 2 channel-halves ---
    float ga = 1.f/(1.f + expf(-bg[0]));
    float ba = 1.f/(1.f + expf(-bb2[0]));
    int px = tid & 127;
    int half = (tid >> 7) & 1;
    int rr = tid >> 8;
    int y = y0 + rr;
    int base[9];
    #pragma unroll
    for(int tap = 0; tap < 9; tap++){
        int dy = tap/3 - 1, dx = tap%3 - 1;
        int yy = y + dy, xx = px + dx;
        int r = 6;
        if(yy >= 0 && yy < 128 && xx >= 0 && xx < 128) r = g_region[(b<<14) + (yy<<7) + xx];
        base[tap] = r*584 + tap*64;
    }
    float nz = g_noiseT[(b<<14) + (y<<7) + px];
    size_t pix = (size_t)(y<<7) + px;
    int drow = (rr*128 + px)*129;
    for(int jj = 0; jj < 8; jj++){
        int j = half*8 + jj;
        unsigned long long ag0=0ull, ag1=0ull, ab0=0ull, ab1=0ull;
        #pragma unroll
        for(int tap = 0; tap < 9; tap++){
            const ulonglong2* pgp = reinterpret_cast<const ulonglong2*>(&tGg[base[tap] + j*4]);
            const ulonglong2* pbp = reinterpret_cast<const ulonglong2*>(&tGb[base[tap] + j*4]);
            ulonglong2 vg = *pgp, vb = *pbp;
            add2(ag0, vg.x); add2(ag1, vg.y);
            add2(ab0, vb.x); add2(ab1, vb.y);
        }
        float g4[4], b4[4];
        upk2(ag0, g4[0], g4[1]); upk2(ag1, g4[2], g4[3]);
        upk2(ab0, b4[0], b4[1]); upk2(ab1, b4[2], b4[3]);
        #pragma unroll
        for(int k = 0; k < 4; k++){
            int c = j*4 + k;
            size_t idx = (((size_t)(b*64 + c))<<14) + pix;
            float xv = x[idx] + s_nv[c]*nz;
            float xn = (xv - s_mean[c])*s_rstd[c];
            float gf = ga*(g4[k] + s_gb[c]) + (1.f - ga)*Dsm[drow + c];
            float bf = ba*(b4[k] + s_bb[c]) + (1.f - ba)*Dsm[drow + 64 + c];
            out[idx] = xn*(1.f + gf) + bf;
        }
    }
}

extern "C" void kernel_launch(void* const* d_in, const int* in_sizes, int n_in,
                              void* d_out, int out_size) {
    const float* x      = (const float*)d_in[0];
    const float* segmap = (const float*)d_in[1];
    const float* mask   = (const float*)d_in[2];
    const float* codes  = (const float*)d_in[3];
    const float* noise  = (const float*)d_in[4];
    const float* nvar   = (const float*)d_in[5];
    const float* fc_w   = (const float*)d_in[6];
    const float* fc_b   = (const float*)d_in[7];
    const float* cg_w   = (const float*)d_in[8];
    const float* cg_b   = (const float*)d_in[9];
    const float* cb_w   = (const float*)d_in[10];
    const float* cb_b   = (const float*)d_in[11];
    const float* ss_w   = (const float*)d_in[12];
    const float* ss_b   = (const float*)d_in[13];
    const float* sg_w   = (const float*)d_in[14];
    const float* sg_b   = (const float*)d_in[15];
    const float* sb_w   = (const float*)d_in[16];
    const float* sb_b   = (const float*)d_in[17];
    const float* bgam   = (const float*)d_in[18];
    const float* bbet   = (const float*)d_in[19];
    float* out = (float*)d_out;

    cudaFuncSetAttribute(spade_fused_kernel,
                         cudaFuncAttributeMaxDynamicSharedMemorySize, SPADE_SMEM);
    cudaFuncSetAttribute(gtab_actv_stats_kernel,
                         cudaFuncAttributeMaxDynamicSharedMemorySize, GTAB_SMEM);

    fusedprep_kernel<<<1088, 256>>>(sg_w, sb_w, segmap, noise);
    mmu_kernel<<<dim3(24,8), 256>>>(codes, fc_w, fc_b);
    gtab_actv_stats_kernel<<<640, 256, GTAB_SMEM>>>(cg_w, cb_w, mask, ss_w, ss_b, x, nvar);
    spade_fused_kernel<<<dim3(64,4), 512, SPADE_SMEM>>>(
        x, nvar, sg_b, sb_b, cg_b, cb_b, bgam, bbet, out);
}